// round 3
// baseline (speedup 1.0000x reference)
#include <cuda_runtime.h>
#include <cuda_bf16.h>
#include <math.h>

// Problem constants
#define T_TOK 2048        // B*S
#define D_DIM 1024
#define H_DIM 4096
#define E_NUM 8
#define TOPK 2
#define N_SLOTS (T_TOK * TOPK)   // 4096
#define OUT_ELEMS (T_TOK * D_DIM) // 2097152

// ---------------- device scratch (static, allocation-free) ----------------
__device__ int   g_counts[E_NUM];
__device__ int   g_offsets[E_NUM + 1];
__device__ int   g_cursor[E_NUM];
__device__ int   g_slot_tok[N_SLOTS];
__device__ float g_slot_prob[N_SLOTS];
__device__ int   g_tok_slot[T_TOK * TOPK];
__device__ int   g_top_e[T_TOK * TOPK];
__device__ float g_top_p[T_TOK * TOPK];
__device__ float g_probs8[T_TOK * E_NUM];
__device__ __align__(16) float g_H[(size_t)N_SLOTS * H_DIM];   // 64 MB fc1 activations
__device__ __align__(16) float g_Y[(size_t)N_SLOTS * D_DIM];   // 16 MB fc2 outputs (prob-scaled)

// ---------------- init ----------------
__global__ void init_kernel() {
    if (threadIdx.x < E_NUM) g_counts[threadIdx.x] = 0;
}

// ---------------- router: one block per token, 128 threads ----------------
__global__ void router_kernel(const float* __restrict__ x,
                              const float* __restrict__ Wg) {
    const int t = blockIdx.x;
    const float* xr = x + (size_t)t * D_DIM;
    float acc[E_NUM];
#pragma unroll
    for (int e = 0; e < E_NUM; e++) acc[e] = 0.f;

    for (int d = threadIdx.x; d < D_DIM; d += 128) {
        float xv = xr[d];
#pragma unroll
        for (int e = 0; e < E_NUM; e++)
            acc[e] = fmaf(xv, Wg[e * D_DIM + d], acc[e]);
    }
    // warp reduce
#pragma unroll
    for (int e = 0; e < E_NUM; e++)
#pragma unroll
        for (int off = 16; off > 0; off >>= 1)
            acc[e] += __shfl_xor_sync(0xffffffffu, acc[e], off);

    __shared__ float s[E_NUM][4];
    const int warp = threadIdx.x >> 5, lane = threadIdx.x & 31;
    if (lane == 0)
#pragma unroll
        for (int e = 0; e < E_NUM; e++) s[e][warp] = acc[e];
    __syncthreads();

    if (threadIdx.x == 0) {
        float lg[E_NUM];
#pragma unroll
        for (int e = 0; e < E_NUM; e++)
            lg[e] = s[e][0] + s[e][1] + s[e][2] + s[e][3];
        // full softmax (for aux loss)
        float mx = lg[0];
#pragma unroll
        for (int e = 1; e < E_NUM; e++) mx = fmaxf(mx, lg[e]);
        float se = 0.f, pe[E_NUM];
#pragma unroll
        for (int e = 0; e < E_NUM; e++) { pe[e] = expf(lg[e] - mx); se += pe[e]; }
        float inv = 1.f / se;
#pragma unroll
        for (int e = 0; e < E_NUM; e++) g_probs8[t * E_NUM + e] = pe[e] * inv;
        // top-2 (jax top_k: largest value; ties -> lowest index first)
        int i1 = 0;
#pragma unroll
        for (int e = 1; e < E_NUM; e++) if (lg[e] > lg[i1]) i1 = e;
        int i2 = -1;
#pragma unroll
        for (int e = 0; e < E_NUM; e++) {
            if (e == i1) continue;
            if (i2 < 0 || lg[e] > lg[i2]) i2 = e;
        }
        float v1 = lg[i1], v2 = lg[i2];
        float m = fmaxf(v1, v2);
        float e1 = expf(v1 - m), e2 = expf(v2 - m);
        float denom = 1.f / (e1 + e2);
        g_top_e[t * 2 + 0] = i1;  g_top_e[t * 2 + 1] = i2;
        g_top_p[t * 2 + 0] = e1 * denom;
        g_top_p[t * 2 + 1] = e2 * denom;
        atomicAdd(&g_counts[i1], 1);
        atomicAdd(&g_counts[i2], 1);
    }
}

// ---------------- prefix sum over 8 experts ----------------
__global__ void offsets_kernel() {
    if (threadIdx.x == 0) {
        int o = 0;
        for (int e = 0; e < E_NUM; e++) {
            g_offsets[e] = o; g_cursor[e] = o; o += g_counts[e];
        }
        g_offsets[E_NUM] = o;
    }
}

// ---------------- scatter tokens into expert buckets ----------------
__global__ void scatter_kernel() {
    int t = blockIdx.x * blockDim.x + threadIdx.x;
    if (t >= T_TOK) return;
#pragma unroll
    for (int k = 0; k < TOPK; k++) {
        int e = g_top_e[t * 2 + k];
        int sidx = atomicAdd(&g_cursor[e], 1);
        g_slot_tok[sidx]  = t;
        g_slot_prob[sidx] = g_top_p[t * 2 + k];
        g_tok_slot[t * 2 + k] = sidx;
    }
}

// ---------------- aux loss (deterministic reduction) ----------------
__global__ void aux_kernel(float* __restrict__ out, int out_size) {
    __shared__ float red[E_NUM][256];
    float ls[E_NUM];
#pragma unroll
    for (int e = 0; e < E_NUM; e++) ls[e] = 0.f;
    for (int t = threadIdx.x; t < T_TOK; t += 256)
#pragma unroll
        for (int e = 0; e < E_NUM; e++) ls[e] += g_probs8[t * E_NUM + e];
#pragma unroll
    for (int e = 0; e < E_NUM; e++) red[e][threadIdx.x] = ls[e];
    __syncthreads();
    for (int st = 128; st > 0; st >>= 1) {
        if (threadIdx.x < st)
#pragma unroll
            for (int e = 0; e < E_NUM; e++)
                red[e][threadIdx.x] += red[e][threadIdx.x + st];
        __syncthreads();
    }
    if (threadIdx.x == 0 && out_size > OUT_ELEMS) {
        float aux = 0.f;
        for (int e = 0; e < E_NUM; e++)
            aux += (red[e][0] / (float)T_TOK) * ((float)g_counts[e] / (float)T_TOK);
        out[OUT_ELEMS] = (float)E_NUM * aux;
    }
}

// ---------------- grouped expert GEMM (128x128 tile, 8x8/thread) ----------------
// FC1:  C = g_H, A = x gathered via g_slot_tok, relu epilogue
// FC2:  C = g_Y, A = g_H (slot rows), prob-scale epilogue
// All scratch referenced as device symbols IN DEVICE CODE (never as host args).
template <int N_DIM, int K_DIM, bool FC1>
__global__ __launch_bounds__(256, 2)
void expert_gemm(const float* __restrict__ Xsrc, const float* __restrict__ Wfull,
                 const float* __restrict__ bias) {
    const int e = blockIdx.z;
    const int row_beg = g_offsets[e];
    const int row_end = g_offsets[e + 1];
    const int m0 = row_beg + blockIdx.y * 128;
    if (m0 >= row_end) return;
    const int n0 = blockIdx.x * 128;
    const float* W = Wfull + (size_t)e * N_DIM * K_DIM;
    const float* Abase = FC1 ? Xsrc : g_H;
    float* Cdst = FC1 ? g_H : g_Y;

    __shared__ float As[16][128];
    __shared__ float Bs[16][128];

    const int tid = threadIdx.x;

    const float* rowA[2];
    const float* rowB[2];
#pragma unroll
    for (int i = 0; i < 2; i++) {
        int l = tid + 256 * i;
        int m = l >> 2;
        int kq4 = (l & 3) * 4;
        int row = m0 + m;
        int arow;
        if (FC1) {
            arow = (row < row_end) ? g_slot_tok[row] : g_slot_tok[m0];
        } else {
            arow = (row < row_end) ? row : m0;
        }
        rowA[i] = Abase + (size_t)arow * K_DIM + kq4;
        rowB[i] = W + (size_t)(n0 + m) * K_DIM + kq4;
    }

    float acc[8][8];
#pragma unroll
    for (int i = 0; i < 8; i++)
#pragma unroll
        for (int j = 0; j < 8; j++) acc[i][j] = 0.f;

    const int tx = tid & 15, ty = tid >> 4;

    for (int k0 = 0; k0 < K_DIM; k0 += 16) {
        __syncthreads();
#pragma unroll
        for (int i = 0; i < 2; i++) {
            int l = tid + 256 * i;
            int m = l >> 2, kq = l & 3;
            float4 va = *(const float4*)(rowA[i] + k0);
            As[kq * 4 + 0][m] = va.x; As[kq * 4 + 1][m] = va.y;
            As[kq * 4 + 2][m] = va.z; As[kq * 4 + 3][m] = va.w;
            float4 vb = *(const float4*)(rowB[i] + k0);
            Bs[kq * 4 + 0][m] = vb.x; Bs[kq * 4 + 1][m] = vb.y;
            Bs[kq * 4 + 2][m] = vb.z; Bs[kq * 4 + 3][m] = vb.w;
        }
        __syncthreads();
#pragma unroll
        for (int k = 0; k < 16; k++) {
            float a[8], b[8];
            *(float4*)(a)     = *(const float4*)&As[k][ty * 8];
            *(float4*)(a + 4) = *(const float4*)&As[k][ty * 8 + 4];
            *(float4*)(b)     = *(const float4*)&Bs[k][tx * 8];
            *(float4*)(b + 4) = *(const float4*)&Bs[k][tx * 8 + 4];
#pragma unroll
            for (int i = 0; i < 8; i++)
#pragma unroll
                for (int j = 0; j < 8; j++)
                    acc[i][j] = fmaf(a[i], b[j], acc[i][j]);
        }
    }

    // epilogue
#pragma unroll
    for (int i = 0; i < 8; i++) {
        int row = m0 + ty * 8 + i;
        if (row >= row_end) continue;
        float scale = FC1 ? 1.f : g_slot_prob[row];
        float* cp = Cdst + (size_t)row * N_DIM + n0 + tx * 8;
#pragma unroll
        for (int jq = 0; jq < 2; jq++) {
            float vv[4];
#pragma unroll
            for (int j = 0; j < 4; j++) {
                float c = acc[i][jq * 4 + j] + bias[e * N_DIM + n0 + tx * 8 + jq * 4 + j];
                if (FC1) c = fmaxf(c, 0.f);
                vv[j] = c * scale;
            }
            *(float4*)(cp + jq * 4) = make_float4(vv[0], vv[1], vv[2], vv[3]);
        }
    }
}

// ---------------- combine: out[t] = Y[slot0(t)] + Y[slot1(t)] ----------------
__global__ void combine_kernel(float* __restrict__ out) {
    const int t = blockIdx.x;
    const int s0 = g_tok_slot[t * 2 + 0];
    const int s1 = g_tok_slot[t * 2 + 1];
    const float4* y0 = (const float4*)(g_Y + (size_t)s0 * D_DIM);
    const float4* y1 = (const float4*)(g_Y + (size_t)s1 * D_DIM);
    float4* o = (float4*)(out + (size_t)t * D_DIM);
    int i = threadIdx.x;  // 256 threads, 256 float4 per row
    float4 a = y0[i], b = y1[i];
    o[i] = make_float4(a.x + b.x, a.y + b.y, a.z + b.z, a.w + b.w);
}

// ---------------- launch ----------------
extern "C" void kernel_launch(void* const* d_in, const int* in_sizes, int n_in,
                              void* d_out, int out_size) {
    const float* x  = (const float*)d_in[0];   // [2,1024,1024]
    const float* Wg = (const float*)d_in[1];   // [8,1024]
    const float* W1 = (const float*)d_in[2];   // [8,4096,1024]
    const float* b1 = (const float*)d_in[3];   // [8,4096]
    const float* W2 = (const float*)d_in[4];   // [8,1024,4096]
    const float* b2 = (const float*)d_in[5];   // [8,1024]
    float* out = (float*)d_out;

    init_kernel<<<1, 32>>>();
    router_kernel<<<T_TOK, 128>>>(x, Wg);
    offsets_kernel<<<1, 32>>>();
    scatter_kernel<<<(T_TOK + 255) / 256, 256>>>();
    aux_kernel<<<1, 256>>>(out, out_size);

    // fc1: [slots, 1024] @ W1[e]^T -> relu -> g_H [slots, 4096]
    {
        dim3 grid(H_DIM / 128, (T_TOK + 127) / 128, E_NUM);  // worst case rows_e = 2048
        expert_gemm<H_DIM, D_DIM, true><<<grid, 256>>>(x, W1, b1);
    }
    // fc2: g_H [slots, 4096] @ W2[e]^T -> * prob -> g_Y [slots, 1024]
    {
        dim3 grid(D_DIM / 128, (T_TOK + 127) / 128, E_NUM);
        expert_gemm<D_DIM, H_DIM, false><<<grid, 256>>>(x, W2, b2);
    }
    combine_kernel<<<T_TOK, 256>>>(out);
}

// round 6
// speedup vs baseline: 2.0599x; 2.0599x over previous
#include <cuda_runtime.h>
#include <cuda_bf16.h>
#include <math.h>
#include <stdint.h>

// Problem constants
#define T_TOK 2048        // B*S
#define D_DIM 1024
#define H_DIM 4096
#define E_NUM 8
#define TOPK 2
#define N_SLOTS (T_TOK * TOPK)    // 4096
#define OUT_ELEMS (T_TOK * D_DIM) // 2097152

// ---------------- device scratch (static, allocation-free) ----------------
__device__ int   g_counts[E_NUM];
__device__ int   g_offsets[E_NUM + 1];
__device__ int   g_cursor[E_NUM];
__device__ int   g_slot_tok[N_SLOTS];
__device__ float g_slot_prob[N_SLOTS];
__device__ int   g_tok_slot[T_TOK * TOPK];
__device__ int   g_top_e[T_TOK * TOPK];
__device__ float g_top_p[T_TOK * TOPK];
__device__ float g_probs8[T_TOK * E_NUM];

__device__ __align__(16) __nv_bfloat16 g_xhi[(size_t)T_TOK * D_DIM];
__device__ __align__(16) __nv_bfloat16 g_xlo[(size_t)T_TOK * D_DIM];
__device__ __align__(16) __nv_bfloat16 g_W1hi[(size_t)E_NUM * H_DIM * D_DIM];
__device__ __align__(16) __nv_bfloat16 g_W1lo[(size_t)E_NUM * H_DIM * D_DIM];
__device__ __align__(16) __nv_bfloat16 g_W2hi[(size_t)E_NUM * D_DIM * H_DIM];
__device__ __align__(16) __nv_bfloat16 g_W2lo[(size_t)E_NUM * D_DIM * H_DIM];
__device__ __align__(16) __nv_bfloat16 g_Hhi[(size_t)N_SLOTS * H_DIM];
__device__ __align__(16) __nv_bfloat16 g_Hlo[(size_t)N_SLOTS * H_DIM];
__device__ __align__(16) float g_Y[(size_t)N_SLOTS * D_DIM];

// ---------------- PTX helpers (sm_80-class only; no 'a' features) ----------------
__device__ __forceinline__ uint32_t smem_u32(const void* p) {
    return (uint32_t)__cvta_generic_to_shared(p);
}

__device__ __forceinline__ void cp16(uint32_t saddr, const void* gaddr) {
    asm volatile("cp.async.cg.shared.global [%0], [%1], 16;" :: "r"(saddr), "l"(gaddr));
}
#define CP_COMMIT() asm volatile("cp.async.commit_group;" ::: "memory")
#define CP_WAIT2()  asm volatile("cp.async.wait_group 2;" ::: "memory")

__device__ __forceinline__ void ldsm_x4(uint32_t* r, uint32_t addr) {
    asm volatile("ldmatrix.sync.aligned.m8n8.x4.shared.b16 {%0,%1,%2,%3}, [%4];"
        : "=r"(r[0]), "=r"(r[1]), "=r"(r[2]), "=r"(r[3]) : "r"(addr));
}
__device__ __forceinline__ void ldsm_x2(uint32_t* r, uint32_t addr) {
    asm volatile("ldmatrix.sync.aligned.m8n8.x2.shared.b16 {%0,%1}, [%2];"
        : "=r"(r[0]), "=r"(r[1]) : "r"(addr));
}

__device__ __forceinline__ void mma16816(float* d, const uint32_t* a, const uint32_t* b) {
    asm volatile(
        "mma.sync.aligned.m16n8k16.row.col.f32.bf16.bf16.f32 "
        "{%0,%1,%2,%3}, {%4,%5,%6,%7}, {%8,%9}, {%0,%1,%2,%3};"
        : "+f"(d[0]), "+f"(d[1]), "+f"(d[2]), "+f"(d[3])
        : "r"(a[0]), "r"(a[1]), "r"(a[2]), "r"(a[3]), "r"(b[0]), "r"(b[1]));
}

// ---------------- init ----------------
__global__ void init_kernel() {
    if (threadIdx.x < E_NUM) g_counts[threadIdx.x] = 0;
}

// ---------------- router ----------------
__global__ void router_kernel(const float* __restrict__ x,
                              const float* __restrict__ Wg) {
    const int t = blockIdx.x;
    const float* xr = x + (size_t)t * D_DIM;
    float acc[E_NUM];
#pragma unroll
    for (int e = 0; e < E_NUM; e++) acc[e] = 0.f;

    for (int d = threadIdx.x; d < D_DIM; d += 128) {
        float xv = xr[d];
#pragma unroll
        for (int e = 0; e < E_NUM; e++)
            acc[e] = fmaf(xv, Wg[e * D_DIM + d], acc[e]);
    }
#pragma unroll
    for (int e = 0; e < E_NUM; e++)
#pragma unroll
        for (int off = 16; off > 0; off >>= 1)
            acc[e] += __shfl_xor_sync(0xffffffffu, acc[e], off);

    __shared__ float s[E_NUM][4];
    const int warp = threadIdx.x >> 5, lane = threadIdx.x & 31;
    if (lane == 0)
#pragma unroll
        for (int e = 0; e < E_NUM; e++) s[e][warp] = acc[e];
    __syncthreads();

    if (threadIdx.x == 0) {
        float lg[E_NUM];
#pragma unroll
        for (int e = 0; e < E_NUM; e++)
            lg[e] = s[e][0] + s[e][1] + s[e][2] + s[e][3];
        float mx = lg[0];
#pragma unroll
        for (int e = 1; e < E_NUM; e++) mx = fmaxf(mx, lg[e]);
        float se = 0.f, pe[E_NUM];
#pragma unroll
        for (int e = 0; e < E_NUM; e++) { pe[e] = expf(lg[e] - mx); se += pe[e]; }
        float inv = 1.f / se;
#pragma unroll
        for (int e = 0; e < E_NUM; e++) g_probs8[t * E_NUM + e] = pe[e] * inv;
        int i1 = 0;
#pragma unroll
        for (int e = 1; e < E_NUM; e++) if (lg[e] > lg[i1]) i1 = e;
        int i2 = -1;
#pragma unroll
        for (int e = 0; e < E_NUM; e++) {
            if (e == i1) continue;
            if (i2 < 0 || lg[e] > lg[i2]) i2 = e;
        }
        float v1 = lg[i1], v2 = lg[i2];
        float m = fmaxf(v1, v2);
        float e1 = expf(v1 - m), e2 = expf(v2 - m);
        float denom = 1.f / (e1 + e2);
        g_top_e[t * 2 + 0] = i1;  g_top_e[t * 2 + 1] = i2;
        g_top_p[t * 2 + 0] = e1 * denom;
        g_top_p[t * 2 + 1] = e2 * denom;
        atomicAdd(&g_counts[i1], 1);
        atomicAdd(&g_counts[i2], 1);
    }
}

__global__ void offsets_kernel() {
    if (threadIdx.x == 0) {
        int o = 0;
        for (int e = 0; e < E_NUM; e++) {
            g_offsets[e] = o; g_cursor[e] = o; o += g_counts[e];
        }
        g_offsets[E_NUM] = o;
    }
}

__global__ void scatter_kernel() {
    int t = blockIdx.x * blockDim.x + threadIdx.x;
    if (t >= T_TOK) return;
#pragma unroll
    for (int k = 0; k < TOPK; k++) {
        int e = g_top_e[t * 2 + k];
        int sidx = atomicAdd(&g_cursor[e], 1);
        g_slot_tok[sidx]  = t;
        g_slot_prob[sidx] = g_top_p[t * 2 + k];
        g_tok_slot[t * 2 + k] = sidx;
    }
}

__global__ void aux_kernel(float* __restrict__ out, int out_size) {
    __shared__ float red[E_NUM][256];
    float ls[E_NUM];
#pragma unroll
    for (int e = 0; e < E_NUM; e++) ls[e] = 0.f;
    for (int t = threadIdx.x; t < T_TOK; t += 256)
#pragma unroll
        for (int e = 0; e < E_NUM; e++) ls[e] += g_probs8[t * E_NUM + e];
#pragma unroll
    for (int e = 0; e < E_NUM; e++) red[e][threadIdx.x] = ls[e];
    __syncthreads();
    for (int st = 128; st > 0; st >>= 1) {
        if (threadIdx.x < st)
#pragma unroll
            for (int e = 0; e < E_NUM; e++)
                red[e][threadIdx.x] += red[e][threadIdx.x + st];
        __syncthreads();
    }
    if (threadIdx.x == 0 && out_size > OUT_ELEMS) {
        float aux = 0.f;
        for (int e = 0; e < E_NUM; e++)
            aux += (red[e][0] / (float)T_TOK) * ((float)g_counts[e] / (float)T_TOK);
        out[OUT_ELEMS] = (float)E_NUM * aux;
    }
}

// ---------------- fp32 -> bf16 hi/lo split ----------------
__global__ void split_kernel(const float4* __restrict__ src,
                             uint2* __restrict__ hi, uint2* __restrict__ lo, int n4) {
    int i = blockIdx.x * blockDim.x + threadIdx.x;
    int stride = gridDim.x * blockDim.x;
    for (; i < n4; i += stride) {
        float4 v = src[i];
        __nv_bfloat16 h0 = __float2bfloat16(v.x), h1 = __float2bfloat16(v.y);
        __nv_bfloat16 h2 = __float2bfloat16(v.z), h3 = __float2bfloat16(v.w);
        __nv_bfloat16 l0 = __float2bfloat16(v.x - __bfloat162float(h0));
        __nv_bfloat16 l1 = __float2bfloat16(v.y - __bfloat162float(h1));
        __nv_bfloat16 l2 = __float2bfloat16(v.z - __bfloat162float(h2));
        __nv_bfloat16 l3 = __float2bfloat16(v.w - __bfloat162float(h3));
        uint2 hv, lv;
        hv.x = (uint32_t)__bfloat16_as_ushort(h0) | ((uint32_t)__bfloat16_as_ushort(h1) << 16);
        hv.y = (uint32_t)__bfloat16_as_ushort(h2) | ((uint32_t)__bfloat16_as_ushort(h3) << 16);
        lv.x = (uint32_t)__bfloat16_as_ushort(l0) | ((uint32_t)__bfloat16_as_ushort(l1) << 16);
        lv.y = (uint32_t)__bfloat16_as_ushort(l2) | ((uint32_t)__bfloat16_as_ushort(l3) << 16);
        hi[i] = hv;
        lo[i] = lv;
    }
}

// ---------------- mma.sync grouped expert GEMM ----------------
// Block tile 128x128, K=32/stage, 3-stage cp.async pipeline.
// 8 warps: warp_m = wid>>2 (64 rows), warp_n = wid&3 (32 cols).
// bf16x3: acc += Ah*Bh + Ah*Bl + Al*Bh  (fp32 accum).
// smem tile row stride = 40 bf16 (80B) -> conflict-free ldmatrix.

#define KCHUNK 32
#define ROWPAD 40                       // elements per smem row
#define TILE_B (128 * ROWPAD * 2)       // 10240 bytes per tile
#define OFF_AHI 0
#define OFF_ALO (1 * TILE_B)
#define OFF_BHI (2 * TILE_B)
#define OFF_BLO (3 * TILE_B)
#define STAGE_B (4 * TILE_B)            // 40960 bytes per stage
#define NSTAGE 3
#define SMEM_TOTAL (NSTAGE * STAGE_B)   // 122880

template <int N_DIM, int K_DIM, bool FC1>
__global__ void __launch_bounds__(256, 1)
expert_gemm_mma(const __nv_bfloat16* __restrict__ Ahi_g,
                const __nv_bfloat16* __restrict__ Alo_g,
                const __nv_bfloat16* __restrict__ Bhi_g,
                const __nv_bfloat16* __restrict__ Blo_g,
                const float* __restrict__ bias,
                __nv_bfloat16* __restrict__ Hhi_out,
                __nv_bfloat16* __restrict__ Hlo_out,
                float* __restrict__ Y_out) {
    constexpr int NC = K_DIM / KCHUNK;

    const int e = blockIdx.z;
    const int row_beg = g_offsets[e];
    const int row_end = g_offsets[e + 1];
    const int m0 = row_beg + blockIdx.y * 128;
    if (m0 >= row_end) return;
    const int n0 = blockIdx.x * 128;

    const __nv_bfloat16* Bhi = Bhi_g + (size_t)e * N_DIM * K_DIM;
    const __nv_bfloat16* Blo = Blo_g + (size_t)e * N_DIM * K_DIM;
    const float* biasE = bias + e * N_DIM;

    extern __shared__ char smem[];
    const uint32_t smb = smem_u32(smem);
    const int tid = threadIdx.x;
    const int wid = tid >> 5;
    const int lane = tid & 31;
    const int warp_m = wid >> 2;   // 0..1
    const int warp_n = wid & 3;    // 0..3

    // ---- per-thread cp.async source pointers (2 rows of A, 2 rows of B) ----
    // chunk0 = tid -> row tid>>2 ; chunk1 = tid+256 -> row 64 + (tid>>2)
    const int r0 = tid >> 2;
    const int kc8 = (tid & 3) * 8;   // element offset of this thread's 16B chunk
    const __nv_bfloat16 *gAh[2], *gAl[2], *gBh[2], *gBl[2];
#pragma unroll
    for (int j = 0; j < 2; j++) {
        int r = r0 + 64 * j;
        int rowg = m0 + r;
        int clr = rowg < row_end ? rowg : (row_end - 1);
        int atok = FC1 ? g_slot_tok[clr] : clr;
        gAh[j] = Ahi_g + (size_t)atok * K_DIM + kc8;
        gAl[j] = Alo_g + (size_t)atok * K_DIM + kc8;
        int brow = n0 + r;
        gBh[j] = Bhi + (size_t)brow * K_DIM + kc8;
        gBl[j] = Blo + (size_t)brow * K_DIM + kc8;
    }
    uint32_t soff[2];
#pragma unroll
    for (int j = 0; j < 2; j++)
        soff[j] = (uint32_t)((r0 + 64 * j) * ROWPAD * 2 + (tid & 3) * 16);

    // ---- ldmatrix per-thread base byte offsets ----
    const int l15 = lane & 15;
    const uint32_t aFrag = (uint32_t)(((warp_m * 64 + l15) * ROWPAD + (lane >> 4) * 8) * 2);
    const int l4 = lane & 15;
    const uint32_t bFrag = (uint32_t)(((warp_n * 32 + (l4 & 7)) * ROWPAD + ((l4 >> 3) & 1) * 8) * 2);

    float d[4][4][4];
#pragma unroll
    for (int mi = 0; mi < 4; mi++)
#pragma unroll
        for (int ni = 0; ni < 4; ni++)
#pragma unroll
            for (int q = 0; q < 4; q++) d[mi][ni][q] = 0.f;

    // ---- issue helper (macro to keep literal cp.async) ----
#define ISSUE_STAGE(cidx)                                                        \
    do {                                                                         \
        const uint32_t sb = smb + ((cidx) % NSTAGE) * STAGE_B;                   \
        const int kk = (cidx) * KCHUNK;                                          \
        cp16(sb + OFF_AHI + soff[0], gAh[0] + kk);                               \
        cp16(sb + OFF_AHI + soff[1], gAh[1] + kk);                               \
        cp16(sb + OFF_ALO + soff[0], gAl[0] + kk);                               \
        cp16(sb + OFF_ALO + soff[1], gAl[1] + kk);                               \
        cp16(sb + OFF_BHI + soff[0], gBh[0] + kk);                               \
        cp16(sb + OFF_BHI + soff[1], gBh[1] + kk);                               \
        cp16(sb + OFF_BLO + soff[0], gBl[0] + kk);                               \
        cp16(sb + OFF_BLO + soff[1], gBl[1] + kk);                               \
    } while (0)

    ISSUE_STAGE(0); CP_COMMIT();
    ISSUE_STAGE(1); CP_COMMIT();

    for (int c = 0; c < NC; ++c) {
        if (c + 2 < NC) ISSUE_STAGE(c + 2);
        CP_COMMIT();            // empty group at tail keeps wait_group accounting exact
        CP_WAIT2();
        __syncthreads();

        const uint32_t sb = smb + (c % NSTAGE) * STAGE_B;
        const uint32_t aH = sb + OFF_AHI + aFrag;
        const uint32_t aL = sb + OFF_ALO + aFrag;
        const uint32_t bH = sb + OFF_BHI + bFrag;
        const uint32_t bL = sb + OFF_BLO + bFrag;

#pragma unroll
        for (int ks = 0; ks < 2; ks++) {
            uint32_t Ah[4][4], Al[4][4], Bh[4][2], Bl[4][2];
#pragma unroll
            for (int mi = 0; mi < 4; mi++) {
                ldsm_x4(Ah[mi], aH + mi * (16 * ROWPAD * 2) + ks * 32);
                ldsm_x4(Al[mi], aL + mi * (16 * ROWPAD * 2) + ks * 32);
            }
#pragma unroll
            for (int ni = 0; ni < 4; ni++) {
                ldsm_x2(Bh[ni], bH + ni * (8 * ROWPAD * 2) + ks * 32);
                ldsm_x2(Bl[ni], bL + ni * (8 * ROWPAD * 2) + ks * 32);
            }
#pragma unroll
            for (int mi = 0; mi < 4; mi++)
#pragma unroll
                for (int ni = 0; ni < 4; ni++) {
                    mma16816(d[mi][ni], Ah[mi], Bh[ni]);
                    mma16816(d[mi][ni], Ah[mi], Bl[ni]);
                    mma16816(d[mi][ni], Al[mi], Bh[ni]);
                }
        }
        __syncthreads();
    }

    // ---- epilogue ----
    const int rl = lane >> 2;          // 0..7
    const int cl = (lane & 3) * 2;     // 0,2,4,6
#pragma unroll
    for (int mi = 0; mi < 4; mi++) {
#pragma unroll
        for (int half = 0; half < 2; half++) {
            const int row = m0 + warp_m * 64 + mi * 16 + rl + half * 8;
            if (row >= row_end) continue;
            if (FC1) {
#pragma unroll
                for (int ni = 0; ni < 4; ni++) {
                    const int col = n0 + warp_n * 32 + ni * 8 + cl;
                    float v0 = fmaxf(d[mi][ni][half * 2 + 0] + biasE[col], 0.f);
                    float v1 = fmaxf(d[mi][ni][half * 2 + 1] + biasE[col + 1], 0.f);
                    __nv_bfloat16 h0 = __float2bfloat16(v0), h1 = __float2bfloat16(v1);
                    __nv_bfloat16 l0 = __float2bfloat16(v0 - __bfloat162float(h0));
                    __nv_bfloat16 l1 = __float2bfloat16(v1 - __bfloat162float(h1));
                    uint32_t hp = (uint32_t)__bfloat16_as_ushort(h0) |
                                  ((uint32_t)__bfloat16_as_ushort(h1) << 16);
                    uint32_t lp = (uint32_t)__bfloat16_as_ushort(l0) |
                                  ((uint32_t)__bfloat16_as_ushort(l1) << 16);
                    *(uint32_t*)(Hhi_out + (size_t)row * N_DIM + col) = hp;
                    *(uint32_t*)(Hlo_out + (size_t)row * N_DIM + col) = lp;
                }
            } else {
                const float p = g_slot_prob[row];
#pragma unroll
                for (int ni = 0; ni < 4; ni++) {
                    const int col = n0 + warp_n * 32 + ni * 8 + cl;
                    float2 ov;
                    ov.x = (d[mi][ni][half * 2 + 0] + biasE[col])     * p;
                    ov.y = (d[mi][ni][half * 2 + 1] + biasE[col + 1]) * p;
                    *(float2*)(Y_out + (size_t)row * N_DIM + col) = ov;
                }
            }
        }
    }
#undef ISSUE_STAGE
}

// ---------------- combine ----------------
__global__ void combine_kernel(float* __restrict__ out) {
    const int t = blockIdx.x;
    const int s0 = g_tok_slot[t * 2 + 0];
    const int s1 = g_tok_slot[t * 2 + 1];
    const float4* y0 = (const float4*)(g_Y + (size_t)s0 * D_DIM);
    const float4* y1 = (const float4*)(g_Y + (size_t)s1 * D_DIM);
    float4* o = (float4*)(out + (size_t)t * D_DIM);
    int i = threadIdx.x;
    float4 a = y0[i], b = y1[i];
    o[i] = make_float4(a.x + b.x, a.y + b.y, a.z + b.z, a.w + b.w);
}

// ---------------- launch ----------------
extern "C" void kernel_launch(void* const* d_in, const int* in_sizes, int n_in,
                              void* d_out, int out_size) {
    const float* x  = (const float*)d_in[0];   // [2,1024,1024]
    const float* Wg = (const float*)d_in[1];   // [8,1024]
    const float* W1 = (const float*)d_in[2];   // [8,4096,1024]
    const float* b1 = (const float*)d_in[3];   // [8,4096]
    const float* W2 = (const float*)d_in[4];   // [8,1024,4096]
    const float* b2 = (const float*)d_in[5];   // [8,1024]
    float* out = (float*)d_out;

    void *p_xhi, *p_xlo, *p_w1hi, *p_w1lo, *p_w2hi, *p_w2lo, *p_hhi, *p_hlo, *p_y;
    cudaGetSymbolAddress(&p_xhi, g_xhi);
    cudaGetSymbolAddress(&p_xlo, g_xlo);
    cudaGetSymbolAddress(&p_w1hi, g_W1hi);
    cudaGetSymbolAddress(&p_w1lo, g_W1lo);
    cudaGetSymbolAddress(&p_w2hi, g_W2hi);
    cudaGetSymbolAddress(&p_w2lo, g_W2lo);
    cudaGetSymbolAddress(&p_hhi, g_Hhi);
    cudaGetSymbolAddress(&p_hlo, g_Hlo);
    cudaGetSymbolAddress(&p_y, g_Y);

    cudaFuncSetAttribute(expert_gemm_mma<H_DIM, D_DIM, true>,
                         cudaFuncAttributeMaxDynamicSharedMemorySize, SMEM_TOTAL);
    cudaFuncSetAttribute(expert_gemm_mma<D_DIM, H_DIM, false>,
                         cudaFuncAttributeMaxDynamicSharedMemorySize, SMEM_TOTAL);

    init_kernel<<<1, 32>>>();
    router_kernel<<<T_TOK, 128>>>(x, Wg);
    offsets_kernel<<<1, 32>>>();
    scatter_kernel<<<(T_TOK + 255) / 256, 256>>>();
    aux_kernel<<<1, 256>>>(out, out_size);

    split_kernel<<<512, 256>>>((const float4*)x, (uint2*)p_xhi, (uint2*)p_xlo,
                               (int)((size_t)T_TOK * D_DIM / 4));
    split_kernel<<<2048, 256>>>((const float4*)W1, (uint2*)p_w1hi, (uint2*)p_w1lo,
                                (int)((size_t)E_NUM * H_DIM * D_DIM / 4));
    split_kernel<<<2048, 256>>>((const float4*)W2, (uint2*)p_w2hi, (uint2*)p_w2lo,
                                (int)((size_t)E_NUM * D_DIM * H_DIM / 4));

    // fc1: x[gathered] @ W1^T -> relu -> Hhi/Hlo
    {
        dim3 grid(H_DIM / 128, T_TOK / 128, E_NUM);
        expert_gemm_mma<H_DIM, D_DIM, true><<<grid, 256, SMEM_TOTAL>>>(
            (const __nv_bfloat16*)p_xhi, (const __nv_bfloat16*)p_xlo,
            (const __nv_bfloat16*)p_w1hi, (const __nv_bfloat16*)p_w1lo,
            b1, (__nv_bfloat16*)p_hhi, (__nv_bfloat16*)p_hlo, nullptr);
    }
    // fc2: H @ W2^T -> *prob -> Y
    {
        dim3 grid(D_DIM / 128, T_TOK / 128, E_NUM);
        expert_gemm_mma<D_DIM, H_DIM, false><<<grid, 256, SMEM_TOTAL>>>(
            (const __nv_bfloat16*)p_hhi, (const __nv_bfloat16*)p_hlo,
            (const __nv_bfloat16*)p_w2hi, (const __nv_bfloat16*)p_w2lo,
            b2, nullptr, nullptr, (float*)p_y);
    }
    combine_kernel<<<T_TOK, 256>>>(out);
}

// round 7
// speedup vs baseline: 2.2250x; 1.0802x over previous
#include <cuda_runtime.h>
#include <cuda_bf16.h>
#include <math.h>
#include <stdint.h>

// Problem constants
#define T_TOK 2048        // B*S
#define D_DIM 1024
#define H_DIM 4096
#define E_NUM 8
#define TOPK 2
#define N_SLOTS (T_TOK * TOPK)    // 4096
#define OUT_ELEMS (T_TOK * D_DIM) // 2097152

// ---------------- device scratch (static, allocation-free) ----------------
__device__ int   g_counts[E_NUM];
__device__ int   g_offsets[E_NUM + 1];
__device__ int   g_cursor[E_NUM];
__device__ int   g_slot_tok[N_SLOTS];
__device__ float g_slot_prob[N_SLOTS];
__device__ int   g_tok_slot[T_TOK * TOPK];
__device__ int   g_top_e[T_TOK * TOPK];
__device__ float g_top_p[T_TOK * TOPK];
__device__ float g_probs8[T_TOK * E_NUM];

__device__ __align__(16) __nv_bfloat16 g_xhi[(size_t)T_TOK * D_DIM];
__device__ __align__(16) __nv_bfloat16 g_xlo[(size_t)T_TOK * D_DIM];
__device__ __align__(16) __nv_bfloat16 g_W1hi[(size_t)E_NUM * H_DIM * D_DIM];
__device__ __align__(16) __nv_bfloat16 g_W1lo[(size_t)E_NUM * H_DIM * D_DIM];
__device__ __align__(16) __nv_bfloat16 g_W2hi[(size_t)E_NUM * D_DIM * H_DIM];
__device__ __align__(16) __nv_bfloat16 g_W2lo[(size_t)E_NUM * D_DIM * H_DIM];
__device__ __align__(16) __nv_bfloat16 g_Hhi[(size_t)N_SLOTS * H_DIM];
__device__ __align__(16) __nv_bfloat16 g_Hlo[(size_t)N_SLOTS * H_DIM];
__device__ __align__(16) float g_Y[(size_t)N_SLOTS * D_DIM];

// ---------------- PTX helpers (sm_80-class only; no 'a' features) ----------------
__device__ __forceinline__ uint32_t smem_u32(const void* p) {
    return (uint32_t)__cvta_generic_to_shared(p);
}

__device__ __forceinline__ void cp16(uint32_t saddr, const void* gaddr) {
    asm volatile("cp.async.cg.shared.global [%0], [%1], 16;" :: "r"(saddr), "l"(gaddr));
}
#define CP_COMMIT() asm volatile("cp.async.commit_group;" ::: "memory")
#define CP_WAIT_2() asm volatile("cp.async.wait_group 2;" ::: "memory")

__device__ __forceinline__ void ldsm_x4(uint32_t* r, uint32_t addr) {
    asm volatile("ldmatrix.sync.aligned.m8n8.x4.shared.b16 {%0,%1,%2,%3}, [%4];"
        : "=r"(r[0]), "=r"(r[1]), "=r"(r[2]), "=r"(r[3]) : "r"(addr));
}
__device__ __forceinline__ void ldsm_x2(uint32_t* r, uint32_t addr) {
    asm volatile("ldmatrix.sync.aligned.m8n8.x2.shared.b16 {%0,%1}, [%2];"
        : "=r"(r[0]), "=r"(r[1]) : "r"(addr));
}

__device__ __forceinline__ void mma16816(float* d, const uint32_t* a, const uint32_t* b) {
    asm volatile(
        "mma.sync.aligned.m16n8k16.row.col.f32.bf16.bf16.f32 "
        "{%0,%1,%2,%3}, {%4,%5,%6,%7}, {%8,%9}, {%0,%1,%2,%3};"
        : "+f"(d[0]), "+f"(d[1]), "+f"(d[2]), "+f"(d[3])
        : "r"(a[0]), "r"(a[1]), "r"(a[2]), "r"(a[3]), "r"(b[0]), "r"(b[1]));
}

// ---------------- init ----------------
__global__ void init_kernel() {
    if (threadIdx.x < E_NUM) g_counts[threadIdx.x] = 0;
}

// ---------------- router ----------------
__global__ void router_kernel(const float* __restrict__ x,
                              const float* __restrict__ Wg) {
    const int t = blockIdx.x;
    const float* xr = x + (size_t)t * D_DIM;
    float acc[E_NUM];
#pragma unroll
    for (int e = 0; e < E_NUM; e++) acc[e] = 0.f;

    for (int d = threadIdx.x; d < D_DIM; d += 128) {
        float xv = xr[d];
#pragma unroll
        for (int e = 0; e < E_NUM; e++)
            acc[e] = fmaf(xv, Wg[e * D_DIM + d], acc[e]);
    }
#pragma unroll
    for (int e = 0; e < E_NUM; e++)
#pragma unroll
        for (int off = 16; off > 0; off >>= 1)
            acc[e] += __shfl_xor_sync(0xffffffffu, acc[e], off);

    __shared__ float s[E_NUM][4];
    const int warp = threadIdx.x >> 5, lane = threadIdx.x & 31;
    if (lane == 0)
#pragma unroll
        for (int e = 0; e < E_NUM; e++) s[e][warp] = acc[e];
    __syncthreads();

    if (threadIdx.x == 0) {
        float lg[E_NUM];
#pragma unroll
        for (int e = 0; e < E_NUM; e++)
            lg[e] = s[e][0] + s[e][1] + s[e][2] + s[e][3];
        float mx = lg[0];
#pragma unroll
        for (int e = 1; e < E_NUM; e++) mx = fmaxf(mx, lg[e]);
        float se = 0.f, pe[E_NUM];
#pragma unroll
        for (int e = 0; e < E_NUM; e++) { pe[e] = expf(lg[e] - mx); se += pe[e]; }
        float inv = 1.f / se;
#pragma unroll
        for (int e = 0; e < E_NUM; e++) g_probs8[t * E_NUM + e] = pe[e] * inv;
        int i1 = 0;
#pragma unroll
        for (int e = 1; e < E_NUM; e++) if (lg[e] > lg[i1]) i1 = e;
        int i2 = -1;
#pragma unroll
        for (int e = 0; e < E_NUM; e++) {
            if (e == i1) continue;
            if (i2 < 0 || lg[e] > lg[i2]) i2 = e;
        }
        float v1 = lg[i1], v2 = lg[i2];
        float m = fmaxf(v1, v2);
        float e1 = expf(v1 - m), e2 = expf(v2 - m);
        float denom = 1.f / (e1 + e2);
        g_top_e[t * 2 + 0] = i1;  g_top_e[t * 2 + 1] = i2;
        g_top_p[t * 2 + 0] = e1 * denom;
        g_top_p[t * 2 + 1] = e2 * denom;
        atomicAdd(&g_counts[i1], 1);
        atomicAdd(&g_counts[i2], 1);
    }
}

__global__ void offsets_kernel() {
    if (threadIdx.x == 0) {
        int o = 0;
        for (int e = 0; e < E_NUM; e++) {
            g_offsets[e] = o; g_cursor[e] = o; o += g_counts[e];
        }
        g_offsets[E_NUM] = o;
    }
}

__global__ void scatter_kernel() {
    int t = blockIdx.x * blockDim.x + threadIdx.x;
    if (t >= T_TOK) return;
#pragma unroll
    for (int k = 0; k < TOPK; k++) {
        int e = g_top_e[t * 2 + k];
        int sidx = atomicAdd(&g_cursor[e], 1);
        g_slot_tok[sidx]  = t;
        g_slot_prob[sidx] = g_top_p[t * 2 + k];
        g_tok_slot[t * 2 + k] = sidx;
    }
}

__global__ void aux_kernel(float* __restrict__ out, int out_size) {
    __shared__ float red[E_NUM][256];
    float ls[E_NUM];
#pragma unroll
    for (int e = 0; e < E_NUM; e++) ls[e] = 0.f;
    for (int t = threadIdx.x; t < T_TOK; t += 256)
#pragma unroll
        for (int e = 0; e < E_NUM; e++) ls[e] += g_probs8[t * E_NUM + e];
#pragma unroll
    for (int e = 0; e < E_NUM; e++) red[e][threadIdx.x] = ls[e];
    __syncthreads();
    for (int st = 128; st > 0; st >>= 1) {
        if (threadIdx.x < st)
#pragma unroll
            for (int e = 0; e < E_NUM; e++)
                red[e][threadIdx.x] += red[e][threadIdx.x + st];
        __syncthreads();
    }
    if (threadIdx.x == 0 && out_size > OUT_ELEMS) {
        float aux = 0.f;
        for (int e = 0; e < E_NUM; e++)
            aux += (red[e][0] / (float)T_TOK) * ((float)g_counts[e] / (float)T_TOK);
        out[OUT_ELEMS] = (float)E_NUM * aux;
    }
}

// ---------------- fp32 -> bf16 hi/lo split ----------------
__global__ void split_kernel(const float4* __restrict__ src,
                             uint2* __restrict__ hi, uint2* __restrict__ lo, int n4) {
    int i = blockIdx.x * blockDim.x + threadIdx.x;
    int stride = gridDim.x * blockDim.x;
    for (; i < n4; i += stride) {
        float4 v = src[i];
        __nv_bfloat16 h0 = __float2bfloat16(v.x), h1 = __float2bfloat16(v.y);
        __nv_bfloat16 h2 = __float2bfloat16(v.z), h3 = __float2bfloat16(v.w);
        __nv_bfloat16 l0 = __float2bfloat16(v.x - __bfloat162float(h0));
        __nv_bfloat16 l1 = __float2bfloat16(v.y - __bfloat162float(h1));
        __nv_bfloat16 l2 = __float2bfloat16(v.z - __bfloat162float(h2));
        __nv_bfloat16 l3 = __float2bfloat16(v.w - __bfloat162float(h3));
        uint2 hv, lv;
        hv.x = (uint32_t)__bfloat16_as_ushort(h0) | ((uint32_t)__bfloat16_as_ushort(h1) << 16);
        hv.y = (uint32_t)__bfloat16_as_ushort(h2) | ((uint32_t)__bfloat16_as_ushort(h3) << 16);
        lv.x = (uint32_t)__bfloat16_as_ushort(l0) | ((uint32_t)__bfloat16_as_ushort(l1) << 16);
        lv.y = (uint32_t)__bfloat16_as_ushort(l2) | ((uint32_t)__bfloat16_as_ushort(l3) << 16);
        hi[i] = hv;
        lo[i] = lv;
    }
}

// ---------------- mma.sync grouped expert GEMM ----------------
// Block tile 128x128, K=32/stage, 4-stage cp.async pipeline, prefetch depth 3,
// ONE __syncthreads per K-chunk.
// 8 warps: warp_m = wid>>2 (64 rows), warp_n = wid&3 (32 cols).
// bf16x3: acc += Ah*Bh + Ah*Bl + Al*Bh  (fp32 accum).
// smem tile row stride = 40 bf16 (80B) -> conflict-free ldmatrix.

#define KCHUNK 32
#define ROWPAD 40                       // elements per smem row
#define TILE_B (128 * ROWPAD * 2)       // 10240 bytes per tile
#define OFF_AHI 0
#define OFF_ALO (1 * TILE_B)
#define OFF_BHI (2 * TILE_B)
#define OFF_BLO (3 * TILE_B)
#define STAGE_B (4 * TILE_B)            // 40960 bytes per stage
#define NSTAGE 4
#define SMEM_TOTAL (NSTAGE * STAGE_B)   // 163840

template <int N_DIM, int K_DIM, bool FC1>
__global__ void __launch_bounds__(256, 1)
expert_gemm_mma(const __nv_bfloat16* __restrict__ Ahi_g,
                const __nv_bfloat16* __restrict__ Alo_g,
                const __nv_bfloat16* __restrict__ Bhi_g,
                const __nv_bfloat16* __restrict__ Blo_g,
                const float* __restrict__ bias,
                __nv_bfloat16* __restrict__ Hhi_out,
                __nv_bfloat16* __restrict__ Hlo_out,
                float* __restrict__ Y_out) {
    constexpr int NC = K_DIM / KCHUNK;

    const int e = blockIdx.z;
    const int row_beg = g_offsets[e];
    const int row_end = g_offsets[e + 1];
    const int m0 = row_beg + blockIdx.y * 128;
    if (m0 >= row_end) return;
    const int n0 = blockIdx.x * 128;

    const __nv_bfloat16* Bhi = Bhi_g + (size_t)e * N_DIM * K_DIM;
    const __nv_bfloat16* Blo = Blo_g + (size_t)e * N_DIM * K_DIM;
    const float* biasE = bias + e * N_DIM;

    extern __shared__ char smem[];
    const uint32_t smb = smem_u32(smem);
    const int tid = threadIdx.x;
    const int wid = tid >> 5;
    const int lane = tid & 31;
    const int warp_m = wid >> 2;   // 0..1
    const int warp_n = wid & 3;    // 0..3

    // ---- per-thread cp.async source pointers (2 rows of A, 2 rows of B) ----
    const int r0 = tid >> 2;
    const int kc8 = (tid & 3) * 8;   // element offset of this thread's 16B chunk
    const __nv_bfloat16 *gAh[2], *gAl[2], *gBh[2], *gBl[2];
#pragma unroll
    for (int j = 0; j < 2; j++) {
        int r = r0 + 64 * j;
        int rowg = m0 + r;
        int clr = rowg < row_end ? rowg : (row_end - 1);
        int atok = FC1 ? g_slot_tok[clr] : clr;
        gAh[j] = Ahi_g + (size_t)atok * K_DIM + kc8;
        gAl[j] = Alo_g + (size_t)atok * K_DIM + kc8;
        int brow = n0 + r;
        gBh[j] = Bhi + (size_t)brow * K_DIM + kc8;
        gBl[j] = Blo + (size_t)brow * K_DIM + kc8;
    }
    uint32_t soff[2];
#pragma unroll
    for (int j = 0; j < 2; j++)
        soff[j] = (uint32_t)((r0 + 64 * j) * ROWPAD * 2 + (tid & 3) * 16);

    // ---- ldmatrix per-thread base byte offsets ----
    const int l15 = lane & 15;
    const uint32_t aFrag = (uint32_t)(((warp_m * 64 + l15) * ROWPAD + (lane >> 4) * 8) * 2);
    const uint32_t bFrag = (uint32_t)(((warp_n * 32 + (l15 & 7)) * ROWPAD + ((l15 >> 3) & 1) * 8) * 2);

    float d[4][4][4];
#pragma unroll
    for (int mi = 0; mi < 4; mi++)
#pragma unroll
        for (int ni = 0; ni < 4; ni++)
#pragma unroll
            for (int q = 0; q < 4; q++) d[mi][ni][q] = 0.f;

#define ISSUE_STAGE(cidx)                                                        \
    do {                                                                         \
        const uint32_t sb = smb + ((cidx) % NSTAGE) * STAGE_B;                   \
        const int kk = (cidx) * KCHUNK;                                          \
        cp16(sb + OFF_AHI + soff[0], gAh[0] + kk);                               \
        cp16(sb + OFF_AHI + soff[1], gAh[1] + kk);                               \
        cp16(sb + OFF_ALO + soff[0], gAl[0] + kk);                               \
        cp16(sb + OFF_ALO + soff[1], gAl[1] + kk);                               \
        cp16(sb + OFF_BHI + soff[0], gBh[0] + kk);                               \
        cp16(sb + OFF_BHI + soff[1], gBh[1] + kk);                               \
        cp16(sb + OFF_BLO + soff[0], gBl[0] + kk);                               \
        cp16(sb + OFF_BLO + soff[1], gBl[1] + kk);                               \
    } while (0)

    // prologue: 3 stages in flight
    ISSUE_STAGE(0); CP_COMMIT();
    ISSUE_STAGE(1); CP_COMMIT();
    ISSUE_STAGE(2); CP_COMMIT();

    for (int c = 0; c < NC; ++c) {
        // stage c resident when <=2 younger groups outstanding (uniform accounting:
        // exactly one commit per iteration, empty at the tail)
        CP_WAIT_2();
        __syncthreads();   // also guards buffer (c+3)%4 == (c-1)%4 reuse below

        if (c + 3 < NC) ISSUE_STAGE(c + 3);
        CP_COMMIT();

        const uint32_t sb = smb + (c % NSTAGE) * STAGE_B;
        const uint32_t aH = sb + OFF_AHI + aFrag;
        const uint32_t aL = sb + OFF_ALO + aFrag;
        const uint32_t bH = sb + OFF_BHI + bFrag;
        const uint32_t bL = sb + OFF_BLO + bFrag;

#pragma unroll
        for (int ks = 0; ks < 2; ks++) {
            uint32_t Ah[4][4], Al[4][4], Bh[4][2], Bl[4][2];
#pragma unroll
            for (int mi = 0; mi < 4; mi++) {
                ldsm_x4(Ah[mi], aH + mi * (16 * ROWPAD * 2) + ks * 32);
                ldsm_x4(Al[mi], aL + mi * (16 * ROWPAD * 2) + ks * 32);
            }
#pragma unroll
            for (int ni = 0; ni < 4; ni++) {
                ldsm_x2(Bh[ni], bH + ni * (8 * ROWPAD * 2) + ks * 32);
                ldsm_x2(Bl[ni], bL + ni * (8 * ROWPAD * 2) + ks * 32);
            }
#pragma unroll
            for (int mi = 0; mi < 4; mi++)
#pragma unroll
                for (int ni = 0; ni < 4; ni++) {
                    mma16816(d[mi][ni], Ah[mi], Bh[ni]);
                    mma16816(d[mi][ni], Ah[mi], Bl[ni]);
                    mma16816(d[mi][ni], Al[mi], Bh[ni]);
                }
        }
    }

    // ---- epilogue ----
    const int rl = lane >> 2;          // 0..7
    const int cl = (lane & 3) * 2;     // 0,2,4,6
#pragma unroll
    for (int mi = 0; mi < 4; mi++) {
#pragma unroll
        for (int half = 0; half < 2; half++) {
            const int row = m0 + warp_m * 64 + mi * 16 + rl + half * 8;
            if (row >= row_end) continue;
            if (FC1) {
#pragma unroll
                for (int ni = 0; ni < 4; ni++) {
                    const int col = n0 + warp_n * 32 + ni * 8 + cl;
                    float v0 = fmaxf(d[mi][ni][half * 2 + 0] + biasE[col], 0.f);
                    float v1 = fmaxf(d[mi][ni][half * 2 + 1] + biasE[col + 1], 0.f);
                    __nv_bfloat16 h0 = __float2bfloat16(v0), h1 = __float2bfloat16(v1);
                    __nv_bfloat16 l0 = __float2bfloat16(v0 - __bfloat162float(h0));
                    __nv_bfloat16 l1 = __float2bfloat16(v1 - __bfloat162float(h1));
                    uint32_t hp = (uint32_t)__bfloat16_as_ushort(h0) |
                                  ((uint32_t)__bfloat16_as_ushort(h1) << 16);
                    uint32_t lp = (uint32_t)__bfloat16_as_ushort(l0) |
                                  ((uint32_t)__bfloat16_as_ushort(l1) << 16);
                    *(uint32_t*)(Hhi_out + (size_t)row * N_DIM + col) = hp;
                    *(uint32_t*)(Hlo_out + (size_t)row * N_DIM + col) = lp;
                }
            } else {
                const float p = g_slot_prob[row];
#pragma unroll
                for (int ni = 0; ni < 4; ni++) {
                    const int col = n0 + warp_n * 32 + ni * 8 + cl;
                    float2 ov;
                    ov.x = (d[mi][ni][half * 2 + 0] + biasE[col])     * p;
                    ov.y = (d[mi][ni][half * 2 + 1] + biasE[col + 1]) * p;
                    *(float2*)(Y_out + (size_t)row * N_DIM + col) = ov;
                }
            }
        }
    }
#undef ISSUE_STAGE
}

// ---------------- combine ----------------
__global__ void combine_kernel(float* __restrict__ out) {
    const int t = blockIdx.x;
    const int s0 = g_tok_slot[t * 2 + 0];
    const int s1 = g_tok_slot[t * 2 + 1];
    const float4* y0 = (const float4*)(g_Y + (size_t)s0 * D_DIM);
    const float4* y1 = (const float4*)(g_Y + (size_t)s1 * D_DIM);
    float4* o = (float4*)(out + (size_t)t * D_DIM);
    int i = threadIdx.x;
    float4 a = y0[i], b = y1[i];
    o[i] = make_float4(a.x + b.x, a.y + b.y, a.z + b.z, a.w + b.w);
}

// ---------------- launch ----------------
extern "C" void kernel_launch(void* const* d_in, const int* in_sizes, int n_in,
                              void* d_out, int out_size) {
    const float* x  = (const float*)d_in[0];   // [2,1024,1024]
    const float* Wg = (const float*)d_in[1];   // [8,1024]
    const float* W1 = (const float*)d_in[2];   // [8,4096,1024]
    const float* b1 = (const float*)d_in[3];   // [8,4096]
    const float* W2 = (const float*)d_in[4];   // [8,1024,4096]
    const float* b2 = (const float*)d_in[5];   // [8,1024]
    float* out = (float*)d_out;

    void *p_xhi, *p_xlo, *p_w1hi, *p_w1lo, *p_w2hi, *p_w2lo, *p_hhi, *p_hlo, *p_y;
    cudaGetSymbolAddress(&p_xhi, g_xhi);
    cudaGetSymbolAddress(&p_xlo, g_xlo);
    cudaGetSymbolAddress(&p_w1hi, g_W1hi);
    cudaGetSymbolAddress(&p_w1lo, g_W1lo);
    cudaGetSymbolAddress(&p_w2hi, g_W2hi);
    cudaGetSymbolAddress(&p_w2lo, g_W2lo);
    cudaGetSymbolAddress(&p_hhi, g_Hhi);
    cudaGetSymbolAddress(&p_hlo, g_Hlo);
    cudaGetSymbolAddress(&p_y, g_Y);

    cudaFuncSetAttribute(expert_gemm_mma<H_DIM, D_DIM, true>,
                         cudaFuncAttributeMaxDynamicSharedMemorySize, SMEM_TOTAL);
    cudaFuncSetAttribute(expert_gemm_mma<D_DIM, H_DIM, false>,
                         cudaFuncAttributeMaxDynamicSharedMemorySize, SMEM_TOTAL);

    init_kernel<<<1, 32>>>();
    router_kernel<<<T_TOK, 128>>>(x, Wg);
    offsets_kernel<<<1, 32>>>();
    scatter_kernel<<<(T_TOK + 255) / 256, 256>>>();
    aux_kernel<<<1, 256>>>(out, out_size);

    split_kernel<<<512, 256>>>((const float4*)x, (uint2*)p_xhi, (uint2*)p_xlo,
                               (int)((size_t)T_TOK * D_DIM / 4));
    split_kernel<<<2048, 256>>>((const float4*)W1, (uint2*)p_w1hi, (uint2*)p_w1lo,
                                (int)((size_t)E_NUM * H_DIM * D_DIM / 4));
    split_kernel<<<2048, 256>>>((const float4*)W2, (uint2*)p_w2hi, (uint2*)p_w2lo,
                                (int)((size_t)E_NUM * D_DIM * H_DIM / 4));

    // fc1: x[gathered] @ W1^T -> relu -> Hhi/Hlo
    {
        dim3 grid(H_DIM / 128, T_TOK / 128, E_NUM);
        expert_gemm_mma<H_DIM, D_DIM, true><<<grid, 256, SMEM_TOTAL>>>(
            (const __nv_bfloat16*)p_xhi, (const __nv_bfloat16*)p_xlo,
            (const __nv_bfloat16*)p_w1hi, (const __nv_bfloat16*)p_w1lo,
            b1, (__nv_bfloat16*)p_hhi, (__nv_bfloat16*)p_hlo, nullptr);
    }
    // fc2: H @ W2^T -> *prob -> Y
    {
        dim3 grid(D_DIM / 128, T_TOK / 128, E_NUM);
        expert_gemm_mma<D_DIM, H_DIM, false><<<grid, 256, SMEM_TOTAL>>>(
            (const __nv_bfloat16*)p_hhi, (const __nv_bfloat16*)p_hlo,
            (const __nv_bfloat16*)p_w2hi, (const __nv_bfloat16*)p_w2lo,
            b2, nullptr, nullptr, (float*)p_y);
    }
    combine_kernel<<<T_TOK, 256>>>(out);
}

// round 8
// speedup vs baseline: 2.3906x; 1.0744x over previous
#include <cuda_runtime.h>
#include <cuda_bf16.h>
#include <math.h>
#include <stdint.h>

// Problem constants
#define T_TOK 2048        // B*S
#define D_DIM 1024
#define H_DIM 4096
#define E_NUM 8
#define TOPK 2
#define N_SLOTS (T_TOK * TOPK)    // 4096
#define OUT_ELEMS (T_TOK * D_DIM) // 2097152

// ---------------- device scratch (static, allocation-free) ----------------
__device__ int   g_counts[E_NUM];
__device__ int   g_offsets[E_NUM + 1];
__device__ int   g_cursor[E_NUM];
__device__ int   g_slot_tok[N_SLOTS];
__device__ float g_slot_prob[N_SLOTS];
__device__ int   g_tok_slot[T_TOK * TOPK];
__device__ int   g_top_e[T_TOK * TOPK];
__device__ float g_top_p[T_TOK * TOPK];
__device__ float g_probs8[T_TOK * E_NUM];

__device__ __align__(16) __nv_bfloat16 g_xhi[(size_t)T_TOK * D_DIM];
__device__ __align__(16) __nv_bfloat16 g_xlo[(size_t)T_TOK * D_DIM];
__device__ __align__(16) __nv_bfloat16 g_W1hi[(size_t)E_NUM * H_DIM * D_DIM];
__device__ __align__(16) __nv_bfloat16 g_W1lo[(size_t)E_NUM * H_DIM * D_DIM];
__device__ __align__(16) __nv_bfloat16 g_W2hi[(size_t)E_NUM * D_DIM * H_DIM];
__device__ __align__(16) __nv_bfloat16 g_W2lo[(size_t)E_NUM * D_DIM * H_DIM];
__device__ __align__(16) __nv_bfloat16 g_Hhi[(size_t)N_SLOTS * H_DIM];
__device__ __align__(16) __nv_bfloat16 g_Hlo[(size_t)N_SLOTS * H_DIM];
__device__ __align__(16) float g_Y[(size_t)N_SLOTS * D_DIM];

// ---------------- PTX helpers (sm_80-class only; no 'a' features) ----------------
__device__ __forceinline__ uint32_t smem_u32(const void* p) {
    return (uint32_t)__cvta_generic_to_shared(p);
}

__device__ __forceinline__ void cp16(uint32_t saddr, const void* gaddr) {
    asm volatile("cp.async.cg.shared.global [%0], [%1], 16;" :: "r"(saddr), "l"(gaddr));
}
#define CP_COMMIT() asm volatile("cp.async.commit_group;" ::: "memory")
#define CP_WAIT_1() asm volatile("cp.async.wait_group 1;" ::: "memory")

__device__ __forceinline__ void ldsm_x4(uint32_t* r, uint32_t addr) {
    asm volatile("ldmatrix.sync.aligned.m8n8.x4.shared.b16 {%0,%1,%2,%3}, [%4];"
        : "=r"(r[0]), "=r"(r[1]), "=r"(r[2]), "=r"(r[3]) : "r"(addr));
}
__device__ __forceinline__ void ldsm_x2(uint32_t* r, uint32_t addr) {
    asm volatile("ldmatrix.sync.aligned.m8n8.x2.shared.b16 {%0,%1}, [%2];"
        : "=r"(r[0]), "=r"(r[1]) : "r"(addr));
}

__device__ __forceinline__ void mma16816(float* d, const uint32_t* a, const uint32_t* b) {
    asm volatile(
        "mma.sync.aligned.m16n8k16.row.col.f32.bf16.bf16.f32 "
        "{%0,%1,%2,%3}, {%4,%5,%6,%7}, {%8,%9}, {%0,%1,%2,%3};"
        : "+f"(d[0]), "+f"(d[1]), "+f"(d[2]), "+f"(d[3])
        : "r"(a[0]), "r"(a[1]), "r"(a[2]), "r"(a[3]), "r"(b[0]), "r"(b[1]));
}

// ---------------- init ----------------
__global__ void init_kernel() {
    if (threadIdx.x < E_NUM) g_counts[threadIdx.x] = 0;
}

// ---------------- router ----------------
__global__ void router_kernel(const float* __restrict__ x,
                              const float* __restrict__ Wg) {
    const int t = blockIdx.x;
    const float* xr = x + (size_t)t * D_DIM;
    float acc[E_NUM];
#pragma unroll
    for (int e = 0; e < E_NUM; e++) acc[e] = 0.f;

    for (int d = threadIdx.x; d < D_DIM; d += 128) {
        float xv = xr[d];
#pragma unroll
        for (int e = 0; e < E_NUM; e++)
            acc[e] = fmaf(xv, Wg[e * D_DIM + d], acc[e]);
    }
#pragma unroll
    for (int e = 0; e < E_NUM; e++)
#pragma unroll
        for (int off = 16; off > 0; off >>= 1)
            acc[e] += __shfl_xor_sync(0xffffffffu, acc[e], off);

    __shared__ float s[E_NUM][4];
    const int warp = threadIdx.x >> 5, lane = threadIdx.x & 31;
    if (lane == 0)
#pragma unroll
        for (int e = 0; e < E_NUM; e++) s[e][warp] = acc[e];
    __syncthreads();

    if (threadIdx.x == 0) {
        float lg[E_NUM];
#pragma unroll
        for (int e = 0; e < E_NUM; e++)
            lg[e] = s[e][0] + s[e][1] + s[e][2] + s[e][3];
        float mx = lg[0];
#pragma unroll
        for (int e = 1; e < E_NUM; e++) mx = fmaxf(mx, lg[e]);
        float se = 0.f, pe[E_NUM];
#pragma unroll
        for (int e = 0; e < E_NUM; e++) { pe[e] = expf(lg[e] - mx); se += pe[e]; }
        float inv = 1.f / se;
#pragma unroll
        for (int e = 0; e < E_NUM; e++) g_probs8[t * E_NUM + e] = pe[e] * inv;
        int i1 = 0;
#pragma unroll
        for (int e = 1; e < E_NUM; e++) if (lg[e] > lg[i1]) i1 = e;
        int i2 = -1;
#pragma unroll
        for (int e = 0; e < E_NUM; e++) {
            if (e == i1) continue;
            if (i2 < 0 || lg[e] > lg[i2]) i2 = e;
        }
        float v1 = lg[i1], v2 = lg[i2];
        float m = fmaxf(v1, v2);
        float e1 = expf(v1 - m), e2 = expf(v2 - m);
        float denom = 1.f / (e1 + e2);
        g_top_e[t * 2 + 0] = i1;  g_top_e[t * 2 + 1] = i2;
        g_top_p[t * 2 + 0] = e1 * denom;
        g_top_p[t * 2 + 1] = e2 * denom;
        atomicAdd(&g_counts[i1], 1);
        atomicAdd(&g_counts[i2], 1);
    }
}

__global__ void offsets_kernel() {
    if (threadIdx.x == 0) {
        int o = 0;
        for (int e = 0; e < E_NUM; e++) {
            g_offsets[e] = o; g_cursor[e] = o; o += g_counts[e];
        }
        g_offsets[E_NUM] = o;
    }
}

__global__ void scatter_kernel() {
    int t = blockIdx.x * blockDim.x + threadIdx.x;
    if (t >= T_TOK) return;
#pragma unroll
    for (int k = 0; k < TOPK; k++) {
        int e = g_top_e[t * 2 + k];
        int sidx = atomicAdd(&g_cursor[e], 1);
        g_slot_tok[sidx]  = t;
        g_slot_prob[sidx] = g_top_p[t * 2 + k];
        g_tok_slot[t * 2 + k] = sidx;
    }
}

__global__ void aux_kernel(float* __restrict__ out, int out_size) {
    __shared__ float red[E_NUM][256];
    float ls[E_NUM];
#pragma unroll
    for (int e = 0; e < E_NUM; e++) ls[e] = 0.f;
    for (int t = threadIdx.x; t < T_TOK; t += 256)
#pragma unroll
        for (int e = 0; e < E_NUM; e++) ls[e] += g_probs8[t * E_NUM + e];
#pragma unroll
    for (int e = 0; e < E_NUM; e++) red[e][threadIdx.x] = ls[e];
    __syncthreads();
    for (int st = 128; st > 0; st >>= 1) {
        if (threadIdx.x < st)
#pragma unroll
            for (int e = 0; e < E_NUM; e++)
                red[e][threadIdx.x] += red[e][threadIdx.x + st];
        __syncthreads();
    }
    if (threadIdx.x == 0 && out_size > OUT_ELEMS) {
        float aux = 0.f;
        for (int e = 0; e < E_NUM; e++)
            aux += (red[e][0] / (float)T_TOK) * ((float)g_counts[e] / (float)T_TOK);
        out[OUT_ELEMS] = (float)E_NUM * aux;
    }
}

// ---------------- fp32 -> bf16 hi/lo split ----------------
__global__ void split_kernel(const float4* __restrict__ src,
                             uint2* __restrict__ hi, uint2* __restrict__ lo, int n4) {
    int i = blockIdx.x * blockDim.x + threadIdx.x;
    int stride = gridDim.x * blockDim.x;
    for (; i < n4; i += stride) {
        float4 v = src[i];
        __nv_bfloat16 h0 = __float2bfloat16(v.x), h1 = __float2bfloat16(v.y);
        __nv_bfloat16 h2 = __float2bfloat16(v.z), h3 = __float2bfloat16(v.w);
        __nv_bfloat16 l0 = __float2bfloat16(v.x - __bfloat162float(h0));
        __nv_bfloat16 l1 = __float2bfloat16(v.y - __bfloat162float(h1));
        __nv_bfloat16 l2 = __float2bfloat16(v.z - __bfloat162float(h2));
        __nv_bfloat16 l3 = __float2bfloat16(v.w - __bfloat162float(h3));
        uint2 hv, lv;
        hv.x = (uint32_t)__bfloat16_as_ushort(h0) | ((uint32_t)__bfloat16_as_ushort(h1) << 16);
        hv.y = (uint32_t)__bfloat16_as_ushort(h2) | ((uint32_t)__bfloat16_as_ushort(h3) << 16);
        lv.x = (uint32_t)__bfloat16_as_ushort(l0) | ((uint32_t)__bfloat16_as_ushort(l1) << 16);
        lv.y = (uint32_t)__bfloat16_as_ushort(l2) | ((uint32_t)__bfloat16_as_ushort(l3) << 16);
        hi[i] = hv;
        lo[i] = lv;
    }
}

// ---------------- mma.sync grouped expert GEMM (512 threads) ----------------
// Block tile BM x BN, 16 warps, warp tile 64x32 (warp_m = wid/WN, warp_n = wid%WN).
// K=32 per stage, 3 smem stages, prefetch depth 2 (wait_group 1), one sync/chunk.
// bf16x3: acc += Ah*Bh + Ah*Bl + Al*Bh  (fp32 accum).
// smem rows padded to 40 bf16 (80B) -> conflict-free ldmatrix.

#define KCHUNK 32
#define ROWPAD 40
#define ROWB   (ROWPAD * 2)            // 80 bytes per smem row
#define NSTAGE 3

template <int BM, int BN, int WN, int N_DIM, int K_DIM, bool FC1>
__global__ void __launch_bounds__(512, 1)
expert_gemm_mma2(const __nv_bfloat16* __restrict__ Ahi_g,
                 const __nv_bfloat16* __restrict__ Alo_g,
                 const __nv_bfloat16* __restrict__ Bhi_g,
                 const __nv_bfloat16* __restrict__ Blo_g,
                 const float* __restrict__ bias,
                 __nv_bfloat16* __restrict__ Hhi_out,
                 __nv_bfloat16* __restrict__ Hlo_out,
                 float* __restrict__ Y_out) {
    constexpr int NC = K_DIM / KCHUNK;
    constexpr int ROWS_TOT = BM + BN;                 // 384
    constexpr int OFF_AHI = 0;
    constexpr int OFF_ALO = BM * ROWB;
    constexpr int OFF_BHI = 2 * BM * ROWB;
    constexpr int OFF_BLO = 2 * BM * ROWB + BN * ROWB;
    constexpr int STAGE_B = 2 * ROWS_TOT * ROWB;      // 61440
    constexpr int NJ = ROWS_TOT / 128;                // 3 rows per thread

    const int e = blockIdx.z;
    const int row_beg = g_offsets[e];
    const int row_end = g_offsets[e + 1];
    const int m0 = row_beg + blockIdx.y * BM;
    if (m0 >= row_end) return;
    const int n0 = blockIdx.x * BN;

    const __nv_bfloat16* Bhi = Bhi_g + (size_t)e * N_DIM * K_DIM;
    const __nv_bfloat16* Blo = Blo_g + (size_t)e * N_DIM * K_DIM;
    const float* biasE = bias + e * N_DIM;

    extern __shared__ char smem[];
    const uint32_t smb = smem_u32(smem);
    const int tid = threadIdx.x;
    const int wid = tid >> 5;
    const int lane = tid & 31;
    const int warp_m = wid / WN;
    const int warp_n = wid % WN;

    // ---- per-thread cp.async sources: 3 rows (A or B), hi+lo each ----
    const int r0 = tid >> 2;          // 0..127
    const int c16 = tid & 3;          // 16B chunk in row
    const int kc8 = c16 * 8;
    const __nv_bfloat16 *gHi[NJ], *gLo[NJ];
    uint32_t sOff[NJ];
#pragma unroll
    for (int j = 0; j < NJ; j++) {
        const int r = r0 + 128 * j;
        if (r < BM) {
            int rowg = m0 + r;
            int clr = rowg < row_end ? rowg : (row_end - 1);
            int atok = FC1 ? g_slot_tok[clr] : clr;
            gHi[j] = Ahi_g + (size_t)atok * K_DIM + kc8;
            gLo[j] = Alo_g + (size_t)atok * K_DIM + kc8;
            sOff[j] = (uint32_t)(OFF_AHI + r * ROWB + c16 * 16);
        } else {
            int rb = r - BM;
            int brow = n0 + rb;
            gHi[j] = Bhi + (size_t)brow * K_DIM + kc8;
            gLo[j] = Blo + (size_t)brow * K_DIM + kc8;
            sOff[j] = (uint32_t)(OFF_BHI + rb * ROWB + c16 * 16);
        }
    }
    const uint32_t loDelta = (uint32_t)(OFF_ALO - OFF_AHI);   // == BM*ROWB; B lo delta == BN*ROWB
    const uint32_t loDeltaB = (uint32_t)(OFF_BLO - OFF_BHI);

    // ---- ldmatrix per-thread base byte offsets ----
    const int l15 = lane & 15;
    const uint32_t aFrag = (uint32_t)(OFF_AHI + (warp_m * 64 + l15) * ROWB + (lane >> 4) * 16);
    const uint32_t bFrag = (uint32_t)(OFF_BHI + (warp_n * 32 + (l15 & 7)) * ROWB + ((l15 >> 3) & 1) * 16);

    float d[4][4][4];
#pragma unroll
    for (int mi = 0; mi < 4; mi++)
#pragma unroll
        for (int ni = 0; ni < 4; ni++)
#pragma unroll
            for (int q = 0; q < 4; q++) d[mi][ni][q] = 0.f;

#define ISSUE_STAGE(cidx)                                                          \
    do {                                                                           \
        const uint32_t sb = smb + ((cidx) % NSTAGE) * STAGE_B;                     \
        const int kk = (cidx) * KCHUNK;                                            \
        _Pragma("unroll")                                                          \
        for (int j = 0; j < NJ; j++) {                                             \
            const uint32_t dlo = (r0 + 128 * j < BM) ? loDelta : loDeltaB;         \
            cp16(sb + sOff[j], gHi[j] + kk);                                       \
            cp16(sb + sOff[j] + dlo, gLo[j] + kk);                                 \
        }                                                                          \
    } while (0)

    // prologue: 2 stages in flight
    ISSUE_STAGE(0); CP_COMMIT();
    ISSUE_STAGE(1); CP_COMMIT();

    for (int c = 0; c < NC; ++c) {
        CP_WAIT_1();       // stage c resident (uniform: one commit per iteration)
        __syncthreads();   // also guards reuse of buffer (c+2)%3 (read last iter)

        if (c + 2 < NC) ISSUE_STAGE(c + 2);
        CP_COMMIT();

        const uint32_t sb = smb + (c % NSTAGE) * STAGE_B;
        const uint32_t aH = sb + aFrag;
        const uint32_t aL = aH + loDelta;
        const uint32_t bH = sb + bFrag;
        const uint32_t bL = bH + loDeltaB;

#pragma unroll
        for (int ks = 0; ks < 2; ks++) {
            uint32_t Ah[4][4], Al[4][4], Bh[4][2], Bl[4][2];
#pragma unroll
            for (int mi = 0; mi < 4; mi++) {
                ldsm_x4(Ah[mi], aH + mi * (16 * ROWB) + ks * 32);
                ldsm_x4(Al[mi], aL + mi * (16 * ROWB) + ks * 32);
            }
#pragma unroll
            for (int ni = 0; ni < 4; ni++) {
                ldsm_x2(Bh[ni], bH + ni * (8 * ROWB) + ks * 32);
                ldsm_x2(Bl[ni], bL + ni * (8 * ROWB) + ks * 32);
            }
#pragma unroll
            for (int mi = 0; mi < 4; mi++)
#pragma unroll
                for (int ni = 0; ni < 4; ni++) {
                    mma16816(d[mi][ni], Ah[mi], Bh[ni]);
                    mma16816(d[mi][ni], Ah[mi], Bl[ni]);
                    mma16816(d[mi][ni], Al[mi], Bh[ni]);
                }
        }
    }

    // ---- epilogue ----
    const int rl = lane >> 2;          // 0..7
    const int cl = (lane & 3) * 2;     // 0,2,4,6
#pragma unroll
    for (int mi = 0; mi < 4; mi++) {
#pragma unroll
        for (int half = 0; half < 2; half++) {
            const int row = m0 + warp_m * 64 + mi * 16 + rl + half * 8;
            if (row >= row_end) continue;
            if (FC1) {
#pragma unroll
                for (int ni = 0; ni < 4; ni++) {
                    const int col = n0 + warp_n * 32 + ni * 8 + cl;
                    float v0 = fmaxf(d[mi][ni][half * 2 + 0] + biasE[col], 0.f);
                    float v1 = fmaxf(d[mi][ni][half * 2 + 1] + biasE[col + 1], 0.f);
                    __nv_bfloat16 h0 = __float2bfloat16(v0), h1 = __float2bfloat16(v1);
                    __nv_bfloat16 l0 = __float2bfloat16(v0 - __bfloat162float(h0));
                    __nv_bfloat16 l1 = __float2bfloat16(v1 - __bfloat162float(h1));
                    uint32_t hp = (uint32_t)__bfloat16_as_ushort(h0) |
                                  ((uint32_t)__bfloat16_as_ushort(h1) << 16);
                    uint32_t lp = (uint32_t)__bfloat16_as_ushort(l0) |
                                  ((uint32_t)__bfloat16_as_ushort(l1) << 16);
                    *(uint32_t*)(Hhi_out + (size_t)row * N_DIM + col) = hp;
                    *(uint32_t*)(Hlo_out + (size_t)row * N_DIM + col) = lp;
                }
            } else {
                const float p = g_slot_prob[row];
#pragma unroll
                for (int ni = 0; ni < 4; ni++) {
                    const int col = n0 + warp_n * 32 + ni * 8 + cl;
                    float2 ov;
                    ov.x = (d[mi][ni][half * 2 + 0] + biasE[col])     * p;
                    ov.y = (d[mi][ni][half * 2 + 1] + biasE[col + 1]) * p;
                    *(float2*)(Y_out + (size_t)row * N_DIM + col) = ov;
                }
            }
        }
    }
#undef ISSUE_STAGE
}

#define SMEM_TOTAL2 (NSTAGE * 2 * (128 + 256) * ROWB)   // 184320 (same for both shapes)

// ---------------- combine ----------------
__global__ void combine_kernel(float* __restrict__ out) {
    const int t = blockIdx.x;
    const int s0 = g_tok_slot[t * 2 + 0];
    const int s1 = g_tok_slot[t * 2 + 1];
    const float4* y0 = (const float4*)(g_Y + (size_t)s0 * D_DIM);
    const float4* y1 = (const float4*)(g_Y + (size_t)s1 * D_DIM);
    float4* o = (float4*)(out + (size_t)t * D_DIM);
    int i = threadIdx.x;
    float4 a = y0[i], b = y1[i];
    o[i] = make_float4(a.x + b.x, a.y + b.y, a.z + b.z, a.w + b.w);
}

// ---------------- launch ----------------
extern "C" void kernel_launch(void* const* d_in, const int* in_sizes, int n_in,
                              void* d_out, int out_size) {
    const float* x  = (const float*)d_in[0];   // [2,1024,1024]
    const float* Wg = (const float*)d_in[1];   // [8,1024]
    const float* W1 = (const float*)d_in[2];   // [8,4096,1024]
    const float* b1 = (const float*)d_in[3];   // [8,4096]
    const float* W2 = (const float*)d_in[4];   // [8,1024,4096]
    const float* b2 = (const float*)d_in[5];   // [8,1024]
    float* out = (float*)d_out;

    void *p_xhi, *p_xlo, *p_w1hi, *p_w1lo, *p_w2hi, *p_w2lo, *p_hhi, *p_hlo, *p_y;
    cudaGetSymbolAddress(&p_xhi, g_xhi);
    cudaGetSymbolAddress(&p_xlo, g_xlo);
    cudaGetSymbolAddress(&p_w1hi, g_W1hi);
    cudaGetSymbolAddress(&p_w1lo, g_W1lo);
    cudaGetSymbolAddress(&p_w2hi, g_W2hi);
    cudaGetSymbolAddress(&p_w2lo, g_W2lo);
    cudaGetSymbolAddress(&p_hhi, g_Hhi);
    cudaGetSymbolAddress(&p_hlo, g_Hlo);
    cudaGetSymbolAddress(&p_y, g_Y);

    cudaFuncSetAttribute(expert_gemm_mma2<128, 256, 8, H_DIM, D_DIM, true>,
                         cudaFuncAttributeMaxDynamicSharedMemorySize, SMEM_TOTAL2);
    cudaFuncSetAttribute(expert_gemm_mma2<256, 128, 4, D_DIM, H_DIM, false>,
                         cudaFuncAttributeMaxDynamicSharedMemorySize, SMEM_TOTAL2);

    init_kernel<<<1, 32>>>();
    router_kernel<<<T_TOK, 128>>>(x, Wg);
    offsets_kernel<<<1, 32>>>();
    scatter_kernel<<<(T_TOK + 255) / 256, 256>>>();
    aux_kernel<<<1, 256>>>(out, out_size);

    split_kernel<<<512, 256>>>((const float4*)x, (uint2*)p_xhi, (uint2*)p_xlo,
                               (int)((size_t)T_TOK * D_DIM / 4));
    split_kernel<<<2048, 256>>>((const float4*)W1, (uint2*)p_w1hi, (uint2*)p_w1lo,
                                (int)((size_t)E_NUM * H_DIM * D_DIM / 4));
    split_kernel<<<2048, 256>>>((const float4*)W2, (uint2*)p_w2hi, (uint2*)p_w2lo,
                                (int)((size_t)E_NUM * D_DIM * H_DIM / 4));

    // fc1: x[gathered] @ W1^T -> relu -> Hhi/Hlo   (tile 128x256)
    {
        dim3 grid(H_DIM / 256, T_TOK / 128, E_NUM);
        expert_gemm_mma2<128, 256, 8, H_DIM, D_DIM, true><<<grid, 512, SMEM_TOTAL2>>>(
            (const __nv_bfloat16*)p_xhi, (const __nv_bfloat16*)p_xlo,
            (const __nv_bfloat16*)p_w1hi, (const __nv_bfloat16*)p_w1lo,
            b1, (__nv_bfloat16*)p_hhi, (__nv_bfloat16*)p_hlo, nullptr);
    }
    // fc2: H @ W2^T -> *prob -> Y   (tile 256x128)
    {
        dim3 grid(D_DIM / 128, T_TOK / 256, E_NUM);
        expert_gemm_mma2<256, 128, 4, D_DIM, H_DIM, false><<<grid, 512, SMEM_TOTAL2>>>(
            (const __nv_bfloat16*)p_hhi, (const __nv_bfloat16*)p_hlo,
            (const __nv_bfloat16*)p_w2hi, (const __nv_bfloat16*)p_w2lo,
            b2, nullptr, nullptr, (float*)p_y);
    }
    combine_kernel<<<T_TOK, 256>>>(out);
}

// round 9
// speedup vs baseline: 3.0890x; 1.2922x over previous
#include <cuda_runtime.h>
#include <cuda_fp16.h>
#include <math.h>
#include <stdint.h>

// Problem constants
#define T_TOK 2048        // B*S
#define D_DIM 1024
#define H_DIM 4096
#define E_NUM 8
#define TOPK 2
#define N_SLOTS (T_TOK * TOPK)    // 4096
#define OUT_ELEMS (T_TOK * D_DIM) // 2097152

// ---------------- device scratch (static, allocation-free) ----------------
__device__ int   g_counts[E_NUM];
__device__ int   g_offsets[E_NUM + 1];
__device__ int   g_cursor[E_NUM];
__device__ int   g_slot_tok[N_SLOTS];
__device__ float g_slot_prob[N_SLOTS];
__device__ int   g_tok_slot[T_TOK * TOPK];
__device__ int   g_top_e[T_TOK * TOPK];
__device__ float g_top_p[T_TOK * TOPK];
__device__ float g_probs8[T_TOK * E_NUM];

__device__ __align__(16) __half g_xhi[(size_t)T_TOK * D_DIM];
__device__ __align__(16) __half g_xlo[(size_t)T_TOK * D_DIM];
__device__ __align__(16) __half g_W1h[(size_t)E_NUM * H_DIM * D_DIM];
__device__ __align__(16) __half g_W2h[(size_t)E_NUM * D_DIM * H_DIM];
__device__ __align__(16) __half g_Hhi[(size_t)N_SLOTS * H_DIM];
__device__ __align__(16) __half g_Hlo[(size_t)N_SLOTS * H_DIM];
__device__ __align__(16) float g_Y[(size_t)N_SLOTS * D_DIM];

// ---------------- PTX helpers (sm_80-class only; no 'a' features) ----------------
__device__ __forceinline__ uint32_t smem_u32(const void* p) {
    return (uint32_t)__cvta_generic_to_shared(p);
}

__device__ __forceinline__ void cp16(uint32_t saddr, const void* gaddr) {
    asm volatile("cp.async.cg.shared.global [%0], [%1], 16;" :: "r"(saddr), "l"(gaddr));
}
#define CP_COMMIT() asm volatile("cp.async.commit_group;" ::: "memory")
#define CP_WAIT_2() asm volatile("cp.async.wait_group 2;" ::: "memory")

__device__ __forceinline__ void ldsm_x4(uint32_t* r, uint32_t addr) {
    asm volatile("ldmatrix.sync.aligned.m8n8.x4.shared.b16 {%0,%1,%2,%3}, [%4];"
        : "=r"(r[0]), "=r"(r[1]), "=r"(r[2]), "=r"(r[3]) : "r"(addr));
}
__device__ __forceinline__ void ldsm_x2(uint32_t* r, uint32_t addr) {
    asm volatile("ldmatrix.sync.aligned.m8n8.x2.shared.b16 {%0,%1}, [%2];"
        : "=r"(r[0]), "=r"(r[1]) : "r"(addr));
}

__device__ __forceinline__ void mma16816(float* d, const uint32_t* a, const uint32_t* b) {
    asm volatile(
        "mma.sync.aligned.m16n8k16.row.col.f32.f16.f16.f32 "
        "{%0,%1,%2,%3}, {%4,%5,%6,%7}, {%8,%9}, {%0,%1,%2,%3};"
        : "+f"(d[0]), "+f"(d[1]), "+f"(d[2]), "+f"(d[3])
        : "r"(a[0]), "r"(a[1]), "r"(a[2]), "r"(a[3]), "r"(b[0]), "r"(b[1]));
}

// ---------------- init ----------------
__global__ void init_kernel() {
    if (threadIdx.x < E_NUM) g_counts[threadIdx.x] = 0;
}

// ---------------- router ----------------
__global__ void router_kernel(const float* __restrict__ x,
                              const float* __restrict__ Wg) {
    const int t = blockIdx.x;
    const float* xr = x + (size_t)t * D_DIM;
    float acc[E_NUM];
#pragma unroll
    for (int e = 0; e < E_NUM; e++) acc[e] = 0.f;

    for (int d = threadIdx.x; d < D_DIM; d += 128) {
        float xv = xr[d];
#pragma unroll
        for (int e = 0; e < E_NUM; e++)
            acc[e] = fmaf(xv, Wg[e * D_DIM + d], acc[e]);
    }
#pragma unroll
    for (int e = 0; e < E_NUM; e++)
#pragma unroll
        for (int off = 16; off > 0; off >>= 1)
            acc[e] += __shfl_xor_sync(0xffffffffu, acc[e], off);

    __shared__ float s[E_NUM][4];
    const int warp = threadIdx.x >> 5, lane = threadIdx.x & 31;
    if (lane == 0)
#pragma unroll
        for (int e = 0; e < E_NUM; e++) s[e][warp] = acc[e];
    __syncthreads();

    if (threadIdx.x == 0) {
        float lg[E_NUM];
#pragma unroll
        for (int e = 0; e < E_NUM; e++)
            lg[e] = s[e][0] + s[e][1] + s[e][2] + s[e][3];
        float mx = lg[0];
#pragma unroll
        for (int e = 1; e < E_NUM; e++) mx = fmaxf(mx, lg[e]);
        float se = 0.f, pe[E_NUM];
#pragma unroll
        for (int e = 0; e < E_NUM; e++) { pe[e] = expf(lg[e] - mx); se += pe[e]; }
        float inv = 1.f / se;
#pragma unroll
        for (int e = 0; e < E_NUM; e++) g_probs8[t * E_NUM + e] = pe[e] * inv;
        int i1 = 0;
#pragma unroll
        for (int e = 1; e < E_NUM; e++) if (lg[e] > lg[i1]) i1 = e;
        int i2 = -1;
#pragma unroll
        for (int e = 0; e < E_NUM; e++) {
            if (e == i1) continue;
            if (i2 < 0 || lg[e] > lg[i2]) i2 = e;
        }
        float v1 = lg[i1], v2 = lg[i2];
        float m = fmaxf(v1, v2);
        float e1 = expf(v1 - m), e2 = expf(v2 - m);
        float denom = 1.f / (e1 + e2);
        g_top_e[t * 2 + 0] = i1;  g_top_e[t * 2 + 1] = i2;
        g_top_p[t * 2 + 0] = e1 * denom;
        g_top_p[t * 2 + 1] = e2 * denom;
        atomicAdd(&g_counts[i1], 1);
        atomicAdd(&g_counts[i2], 1);
    }
}

__global__ void offsets_kernel() {
    if (threadIdx.x == 0) {
        int o = 0;
        for (int e = 0; e < E_NUM; e++) {
            g_offsets[e] = o; g_cursor[e] = o; o += g_counts[e];
        }
        g_offsets[E_NUM] = o;
    }
}

__global__ void scatter_kernel() {
    int t = blockIdx.x * blockDim.x + threadIdx.x;
    if (t >= T_TOK) return;
#pragma unroll
    for (int k = 0; k < TOPK; k++) {
        int e = g_top_e[t * 2 + k];
        int sidx = atomicAdd(&g_cursor[e], 1);
        g_slot_tok[sidx]  = t;
        g_slot_prob[sidx] = g_top_p[t * 2 + k];
        g_tok_slot[t * 2 + k] = sidx;
    }
}

__global__ void aux_kernel(float* __restrict__ out, int out_size) {
    __shared__ float red[E_NUM][256];
    float ls[E_NUM];
#pragma unroll
    for (int e = 0; e < E_NUM; e++) ls[e] = 0.f;
    for (int t = threadIdx.x; t < T_TOK; t += 256)
#pragma unroll
        for (int e = 0; e < E_NUM; e++) ls[e] += g_probs8[t * E_NUM + e];
#pragma unroll
    for (int e = 0; e < E_NUM; e++) red[e][threadIdx.x] = ls[e];
    __syncthreads();
    for (int st = 128; st > 0; st >>= 1) {
        if (threadIdx.x < st)
#pragma unroll
            for (int e = 0; e < E_NUM; e++)
                red[e][threadIdx.x] += red[e][threadIdx.x + st];
        __syncthreads();
    }
    if (threadIdx.x == 0 && out_size > OUT_ELEMS) {
        float aux = 0.f;
        for (int e = 0; e < E_NUM; e++)
            aux += (red[e][0] / (float)T_TOK) * ((float)g_counts[e] / (float)T_TOK);
        out[OUT_ELEMS] = (float)E_NUM * aux;
    }
}

// ---------------- fp32 -> fp16 hi/lo split (A-side: x) ----------------
__global__ void split_kernel(const float4* __restrict__ src,
                             uint2* __restrict__ hi, uint2* __restrict__ lo, int n4) {
    int i = blockIdx.x * blockDim.x + threadIdx.x;
    int stride = gridDim.x * blockDim.x;
    for (; i < n4; i += stride) {
        float4 v = src[i];
        __half h0 = __float2half_rn(v.x), h1 = __float2half_rn(v.y);
        __half h2 = __float2half_rn(v.z), h3 = __float2half_rn(v.w);
        __half l0 = __float2half_rn(v.x - __half2float(h0));
        __half l1 = __float2half_rn(v.y - __half2float(h1));
        __half l2 = __float2half_rn(v.z - __half2float(h2));
        __half l3 = __float2half_rn(v.w - __half2float(h3));
        uint2 hv, lv;
        hv.x = (uint32_t)__half_as_ushort(h0) | ((uint32_t)__half_as_ushort(h1) << 16);
        hv.y = (uint32_t)__half_as_ushort(h2) | ((uint32_t)__half_as_ushort(h3) << 16);
        lv.x = (uint32_t)__half_as_ushort(l0) | ((uint32_t)__half_as_ushort(l1) << 16);
        lv.y = (uint32_t)__half_as_ushort(l2) | ((uint32_t)__half_as_ushort(l3) << 16);
        hi[i] = hv;
        lo[i] = lv;
    }
}

// ---------------- fp32 -> fp16 round (B-side: weights, hi only) ----------------
__global__ void round_kernel(const float4* __restrict__ src,
                             uint2* __restrict__ hi, int n4) {
    int i = blockIdx.x * blockDim.x + threadIdx.x;
    int stride = gridDim.x * blockDim.x;
    for (; i < n4; i += stride) {
        float4 v = src[i];
        __half h0 = __float2half_rn(v.x), h1 = __float2half_rn(v.y);
        __half h2 = __float2half_rn(v.z), h3 = __float2half_rn(v.w);
        uint2 hv;
        hv.x = (uint32_t)__half_as_ushort(h0) | ((uint32_t)__half_as_ushort(h1) << 16);
        hv.y = (uint32_t)__half_as_ushort(h2) | ((uint32_t)__half_as_ushort(h3) << 16);
        hi[i] = hv;
    }
}

// ---------------- mma.sync grouped expert GEMM (512 threads, fp16x2) ----------------
// Block tile BM x BN, 16 warps, warp tile 64x32 (warp_m = wid/WN, warp_n = wid%WN).
// K=32 per stage, 4 smem stages, prefetch depth 3, one sync/chunk.
// fp16x2: acc += Ah*Bh + Al*Bh  (A exact to 2^-22 as fp16 pair; B rounded fp16).
// smem rows padded to 40 halves (80B) -> conflict-free ldmatrix.

#define KCHUNK 32
#define ROWPAD 40
#define ROWB   (ROWPAD * 2)            // 80 bytes per smem row
#define NSTAGE 4

template <int BM, int BN, int WN, int N_DIM, int K_DIM, bool FC1>
__global__ void __launch_bounds__(512, 1)
expert_gemm_mma2(const __half* __restrict__ Ahi_g,
                 const __half* __restrict__ Alo_g,
                 const __half* __restrict__ Bh_g,
                 const float* __restrict__ bias,
                 __half* __restrict__ Hhi_out,
                 __half* __restrict__ Hlo_out,
                 float* __restrict__ Y_out) {
    constexpr int NC = K_DIM / KCHUNK;
    constexpr int OFF_AHI = 0;
    constexpr int OFF_ALO = BM * ROWB;
    constexpr int OFF_BH  = 2 * BM * ROWB;
    constexpr int ROWS_TOT = 2 * BM + BN;             // row-loads per stage
    constexpr int STAGE_B = ROWS_TOT * ROWB;
    constexpr int NJ = ROWS_TOT / 128;                // rows per thread (4 or 5)

    const int e = blockIdx.z;
    const int row_beg = g_offsets[e];
    const int row_end = g_offsets[e + 1];
    const int m0 = row_beg + blockIdx.y * BM;
    if (m0 >= row_end) return;
    const int n0 = blockIdx.x * BN;

    const __half* Bh_e = Bh_g + (size_t)e * N_DIM * K_DIM;
    const float* biasE = bias + e * N_DIM;

    extern __shared__ char smem[];
    const uint32_t smb = smem_u32(smem);
    const int tid = threadIdx.x;
    const int wid = tid >> 5;
    const int lane = tid & 31;
    const int warp_m = wid / WN;
    const int warp_n = wid % WN;

    // ---- per-thread cp.async sources: NJ rows, each one 16B chunk ----
    const int r0 = tid >> 2;          // 0..127
    const int c16 = tid & 3;          // 16B chunk in row
    const int kc8 = c16 * 8;          // element offset (8 halves per 16B)
    const __half* gsrc[NJ];
    uint32_t sOff[NJ];
#pragma unroll
    for (int j = 0; j < NJ; j++) {
        const int r = r0 + 128 * j;
        if (r < BM) {
            int rowg = m0 + r;
            int clr = rowg < row_end ? rowg : (row_end - 1);
            int atok = FC1 ? g_slot_tok[clr] : clr;
            gsrc[j] = Ahi_g + (size_t)atok * K_DIM + kc8;
            sOff[j] = (uint32_t)(OFF_AHI + r * ROWB + c16 * 16);
        } else if (r < 2 * BM) {
            int rr = r - BM;
            int rowg = m0 + rr;
            int clr = rowg < row_end ? rowg : (row_end - 1);
            int atok = FC1 ? g_slot_tok[clr] : clr;
            gsrc[j] = Alo_g + (size_t)atok * K_DIM + kc8;
            sOff[j] = (uint32_t)(OFF_ALO + rr * ROWB + c16 * 16);
        } else {
            int rb = r - 2 * BM;
            gsrc[j] = Bh_e + (size_t)(n0 + rb) * K_DIM + kc8;
            sOff[j] = (uint32_t)(OFF_BH + rb * ROWB + c16 * 16);
        }
    }

    // ---- ldmatrix per-thread base byte offsets ----
    const int l15 = lane & 15;
    const uint32_t aFrag = (uint32_t)(OFF_AHI + (warp_m * 64 + l15) * ROWB + (lane >> 4) * 16);
    const uint32_t bFrag = (uint32_t)(OFF_BH + (warp_n * 32 + (l15 & 7)) * ROWB + ((l15 >> 3) & 1) * 16);

    float d[4][4][4];
#pragma unroll
    for (int mi = 0; mi < 4; mi++)
#pragma unroll
        for (int ni = 0; ni < 4; ni++)
#pragma unroll
            for (int q = 0; q < 4; q++) d[mi][ni][q] = 0.f;

#define ISSUE_STAGE(cidx)                                                          \
    do {                                                                           \
        const uint32_t sb = smb + ((cidx) % NSTAGE) * STAGE_B;                     \
        const int kk = (cidx) * KCHUNK;                                            \
        _Pragma("unroll")                                                          \
        for (int j = 0; j < NJ; j++)                                               \
            cp16(sb + sOff[j], gsrc[j] + kk);                                      \
    } while (0)

    // prologue: 3 stages in flight
    ISSUE_STAGE(0); CP_COMMIT();
    ISSUE_STAGE(1); CP_COMMIT();
    ISSUE_STAGE(2); CP_COMMIT();

    for (int c = 0; c < NC; ++c) {
        CP_WAIT_2();       // stage c resident (uniform: one commit per iteration)
        __syncthreads();   // also guards reuse of buffer (c+3)%4 (read last iter)

        if (c + 3 < NC) ISSUE_STAGE(c + 3);
        CP_COMMIT();

        const uint32_t sb = smb + (c % NSTAGE) * STAGE_B;
        const uint32_t aH = sb + aFrag;
        const uint32_t aL = aH + (uint32_t)(OFF_ALO - OFF_AHI);
        const uint32_t bH = sb + bFrag;

#pragma unroll
        for (int ks = 0; ks < 2; ks++) {
            uint32_t Ah[4][4], Al[4][4], Bh[4][2];
#pragma unroll
            for (int mi = 0; mi < 4; mi++) {
                ldsm_x4(Ah[mi], aH + mi * (16 * ROWB) + ks * 32);
                ldsm_x4(Al[mi], aL + mi * (16 * ROWB) + ks * 32);
            }
#pragma unroll
            for (int ni = 0; ni < 4; ni++)
                ldsm_x2(Bh[ni], bH + ni * (8 * ROWB) + ks * 32);
#pragma unroll
            for (int mi = 0; mi < 4; mi++)
#pragma unroll
                for (int ni = 0; ni < 4; ni++) {
                    mma16816(d[mi][ni], Ah[mi], Bh[ni]);
                    mma16816(d[mi][ni], Al[mi], Bh[ni]);
                }
        }
    }

    // ---- epilogue ----
    const int rl = lane >> 2;          // 0..7
    const int cl = (lane & 3) * 2;     // 0,2,4,6
#pragma unroll
    for (int mi = 0; mi < 4; mi++) {
#pragma unroll
        for (int half = 0; half < 2; half++) {
            const int row = m0 + warp_m * 64 + mi * 16 + rl + half * 8;
            if (row >= row_end) continue;
            if (FC1) {
#pragma unroll
                for (int ni = 0; ni < 4; ni++) {
                    const int col = n0 + warp_n * 32 + ni * 8 + cl;
                    float v0 = fmaxf(d[mi][ni][half * 2 + 0] + biasE[col], 0.f);
                    float v1 = fmaxf(d[mi][ni][half * 2 + 1] + biasE[col + 1], 0.f);
                    __half h0 = __float2half_rn(v0), h1 = __float2half_rn(v1);
                    __half l0 = __float2half_rn(v0 - __half2float(h0));
                    __half l1 = __float2half_rn(v1 - __half2float(h1));
                    uint32_t hp = (uint32_t)__half_as_ushort(h0) |
                                  ((uint32_t)__half_as_ushort(h1) << 16);
                    uint32_t lp = (uint32_t)__half_as_ushort(l0) |
                                  ((uint32_t)__half_as_ushort(l1) << 16);
                    *(uint32_t*)(Hhi_out + (size_t)row * N_DIM + col) = hp;
                    *(uint32_t*)(Hlo_out + (size_t)row * N_DIM + col) = lp;
                }
            } else {
                const float p = g_slot_prob[row];
#pragma unroll
                for (int ni = 0; ni < 4; ni++) {
                    const int col = n0 + warp_n * 32 + ni * 8 + cl;
                    float2 ov;
                    ov.x = (d[mi][ni][half * 2 + 0] + biasE[col])     * p;
                    ov.y = (d[mi][ni][half * 2 + 1] + biasE[col + 1]) * p;
                    *(float2*)(Y_out + (size_t)row * N_DIM + col) = ov;
                }
            }
        }
    }
#undef ISSUE_STAGE
}

#define SMEM_FC1 (NSTAGE * (2 * 128 + 256) * ROWB)   // 163840
#define SMEM_FC2 (NSTAGE * (2 * 256 + 128) * ROWB)   // 204800

// ---------------- combine ----------------
__global__ void combine_kernel(float* __restrict__ out) {
    const int t = blockIdx.x;
    const int s0 = g_tok_slot[t * 2 + 0];
    const int s1 = g_tok_slot[t * 2 + 1];
    const float4* y0 = (const float4*)(g_Y + (size_t)s0 * D_DIM);
    const float4* y1 = (const float4*)(g_Y + (size_t)s1 * D_DIM);
    float4* o = (float4*)(out + (size_t)t * D_DIM);
    int i = threadIdx.x;
    float4 a = y0[i], b = y1[i];
    o[i] = make_float4(a.x + b.x, a.y + b.y, a.z + b.z, a.w + b.w);
}

// ---------------- launch ----------------
extern "C" void kernel_launch(void* const* d_in, const int* in_sizes, int n_in,
                              void* d_out, int out_size) {
    const float* x  = (const float*)d_in[0];   // [2,1024,1024]
    const float* Wg = (const float*)d_in[1];   // [8,1024]
    const float* W1 = (const float*)d_in[2];   // [8,4096,1024]
    const float* b1 = (const float*)d_in[3];   // [8,4096]
    const float* W2 = (const float*)d_in[4];   // [8,1024,4096]
    const float* b2 = (const float*)d_in[5];   // [8,1024]
    float* out = (float*)d_out;

    void *p_xhi, *p_xlo, *p_w1h, *p_w2h, *p_hhi, *p_hlo, *p_y;
    cudaGetSymbolAddress(&p_xhi, g_xhi);
    cudaGetSymbolAddress(&p_xlo, g_xlo);
    cudaGetSymbolAddress(&p_w1h, g_W1h);
    cudaGetSymbolAddress(&p_w2h, g_W2h);
    cudaGetSymbolAddress(&p_hhi, g_Hhi);
    cudaGetSymbolAddress(&p_hlo, g_Hlo);
    cudaGetSymbolAddress(&p_y, g_Y);

    cudaFuncSetAttribute(expert_gemm_mma2<128, 256, 8, H_DIM, D_DIM, true>,
                         cudaFuncAttributeMaxDynamicSharedMemorySize, SMEM_FC1);
    cudaFuncSetAttribute(expert_gemm_mma2<256, 128, 4, D_DIM, H_DIM, false>,
                         cudaFuncAttributeMaxDynamicSharedMemorySize, SMEM_FC2);

    init_kernel<<<1, 32>>>();
    router_kernel<<<T_TOK, 128>>>(x, Wg);
    offsets_kernel<<<1, 32>>>();
    scatter_kernel<<<(T_TOK + 255) / 256, 256>>>();
    aux_kernel<<<1, 256>>>(out, out_size);

    split_kernel<<<512, 256>>>((const float4*)x, (uint2*)p_xhi, (uint2*)p_xlo,
                               (int)((size_t)T_TOK * D_DIM / 4));
    round_kernel<<<2048, 256>>>((const float4*)W1, (uint2*)p_w1h,
                                (int)((size_t)E_NUM * H_DIM * D_DIM / 4));
    round_kernel<<<2048, 256>>>((const float4*)W2, (uint2*)p_w2h,
                                (int)((size_t)E_NUM * D_DIM * H_DIM / 4));

    // fc1: x[gathered] @ W1^T -> relu -> Hhi/Hlo   (tile 128x256)
    {
        dim3 grid(H_DIM / 256, T_TOK / 128, E_NUM);
        expert_gemm_mma2<128, 256, 8, H_DIM, D_DIM, true><<<grid, 512, SMEM_FC1>>>(
            (const __half*)p_xhi, (const __half*)p_xlo, (const __half*)p_w1h,
            b1, (__half*)p_hhi, (__half*)p_hlo, nullptr);
    }
    // fc2: H @ W2^T -> *prob -> Y   (tile 256x128)
    {
        dim3 grid(D_DIM / 128, T_TOK / 256, E_NUM);
        expert_gemm_mma2<256, 128, 4, D_DIM, H_DIM, false><<<grid, 512, SMEM_FC2>>>(
            (const __half*)p_hhi, (const __half*)p_hlo, (const __half*)p_w2h,
            b2, nullptr, nullptr, (float*)p_y);
    }
    combine_kernel<<<T_TOK, 256>>>(out);
}

// round 10
// speedup vs baseline: 4.7344x; 1.5326x over previous
#include <cuda_runtime.h>
#include <cuda_fp16.h>
#include <math.h>
#include <stdint.h>

// Problem constants
#define T_TOK 2048        // B*S
#define D_DIM 1024
#define H_DIM 4096
#define E_NUM 8
#define TOPK 2
#define N_SLOTS (T_TOK * TOPK)    // 4096
#define OUT_ELEMS (T_TOK * D_DIM) // 2097152

// ---------------- device scratch (static, allocation-free) ----------------
__device__ int   g_counts[E_NUM];
__device__ int   g_offsets[E_NUM + 1];
__device__ int   g_cursor[E_NUM];
__device__ int   g_slot_tok[N_SLOTS];
__device__ float g_slot_prob[N_SLOTS];
__device__ int   g_tok_slot[T_TOK * TOPK];
__device__ int   g_top_e[T_TOK * TOPK];
__device__ float g_top_p[T_TOK * TOPK];
__device__ float g_probs8[T_TOK * E_NUM];

__device__ __align__(16) __half g_xh[(size_t)T_TOK * D_DIM];
__device__ __align__(16) __half g_W1h[(size_t)E_NUM * H_DIM * D_DIM];
__device__ __align__(16) __half g_W2h[(size_t)E_NUM * D_DIM * H_DIM];
__device__ __align__(16) __half g_Hh[(size_t)N_SLOTS * H_DIM];
__device__ __align__(16) float g_Y[(size_t)N_SLOTS * D_DIM];

// ---------------- PTX helpers (sm_80-class only; no 'a' features) ----------------
__device__ __forceinline__ uint32_t smem_u32(const void* p) {
    return (uint32_t)__cvta_generic_to_shared(p);
}

__device__ __forceinline__ void cp16(uint32_t saddr, const void* gaddr) {
    asm volatile("cp.async.cg.shared.global [%0], [%1], 16;" :: "r"(saddr), "l"(gaddr));
}
#define CP_COMMIT() asm volatile("cp.async.commit_group;" ::: "memory")
#define CP_WAIT_2() asm volatile("cp.async.wait_group 2;" ::: "memory")

__device__ __forceinline__ void ldsm_x4(uint32_t* r, uint32_t addr) {
    asm volatile("ldmatrix.sync.aligned.m8n8.x4.shared.b16 {%0,%1,%2,%3}, [%4];"
        : "=r"(r[0]), "=r"(r[1]), "=r"(r[2]), "=r"(r[3]) : "r"(addr));
}
__device__ __forceinline__ void ldsm_x2(uint32_t* r, uint32_t addr) {
    asm volatile("ldmatrix.sync.aligned.m8n8.x2.shared.b16 {%0,%1}, [%2];"
        : "=r"(r[0]), "=r"(r[1]) : "r"(addr));
}

__device__ __forceinline__ void mma16816(float* d, const uint32_t* a, const uint32_t* b) {
    asm volatile(
        "mma.sync.aligned.m16n8k16.row.col.f32.f16.f16.f32 "
        "{%0,%1,%2,%3}, {%4,%5,%6,%7}, {%8,%9}, {%0,%1,%2,%3};"
        : "+f"(d[0]), "+f"(d[1]), "+f"(d[2]), "+f"(d[3])
        : "r"(a[0]), "r"(a[1]), "r"(a[2]), "r"(a[3]), "r"(b[0]), "r"(b[1]));
}

// ---------------- init ----------------
__global__ void init_kernel() {
    if (threadIdx.x < E_NUM) g_counts[threadIdx.x] = 0;
}

// ---------------- router ----------------
__global__ void router_kernel(const float* __restrict__ x,
                              const float* __restrict__ Wg) {
    const int t = blockIdx.x;
    const float* xr = x + (size_t)t * D_DIM;
    float acc[E_NUM];
#pragma unroll
    for (int e = 0; e < E_NUM; e++) acc[e] = 0.f;

    for (int d = threadIdx.x; d < D_DIM; d += 128) {
        float xv = xr[d];
#pragma unroll
        for (int e = 0; e < E_NUM; e++)
            acc[e] = fmaf(xv, Wg[e * D_DIM + d], acc[e]);
    }
#pragma unroll
    for (int e = 0; e < E_NUM; e++)
#pragma unroll
        for (int off = 16; off > 0; off >>= 1)
            acc[e] += __shfl_xor_sync(0xffffffffu, acc[e], off);

    __shared__ float s[E_NUM][4];
    const int warp = threadIdx.x >> 5, lane = threadIdx.x & 31;
    if (lane == 0)
#pragma unroll
        for (int e = 0; e < E_NUM; e++) s[e][warp] = acc[e];
    __syncthreads();

    if (threadIdx.x == 0) {
        float lg[E_NUM];
#pragma unroll
        for (int e = 0; e < E_NUM; e++)
            lg[e] = s[e][0] + s[e][1] + s[e][2] + s[e][3];
        float mx = lg[0];
#pragma unroll
        for (int e = 1; e < E_NUM; e++) mx = fmaxf(mx, lg[e]);
        float se = 0.f, pe[E_NUM];
#pragma unroll
        for (int e = 0; e < E_NUM; e++) { pe[e] = expf(lg[e] - mx); se += pe[e]; }
        float inv = 1.f / se;
#pragma unroll
        for (int e = 0; e < E_NUM; e++) g_probs8[t * E_NUM + e] = pe[e] * inv;
        int i1 = 0;
#pragma unroll
        for (int e = 1; e < E_NUM; e++) if (lg[e] > lg[i1]) i1 = e;
        int i2 = -1;
#pragma unroll
        for (int e = 0; e < E_NUM; e++) {
            if (e == i1) continue;
            if (i2 < 0 || lg[e] > lg[i2]) i2 = e;
        }
        float v1 = lg[i1], v2 = lg[i2];
        float m = fmaxf(v1, v2);
        float e1 = expf(v1 - m), e2 = expf(v2 - m);
        float denom = 1.f / (e1 + e2);
        g_top_e[t * 2 + 0] = i1;  g_top_e[t * 2 + 1] = i2;
        g_top_p[t * 2 + 0] = e1 * denom;
        g_top_p[t * 2 + 1] = e2 * denom;
        atomicAdd(&g_counts[i1], 1);
        atomicAdd(&g_counts[i2], 1);
    }
}

__global__ void offsets_kernel() {
    if (threadIdx.x == 0) {
        int o = 0;
        for (int e = 0; e < E_NUM; e++) {
            g_offsets[e] = o; g_cursor[e] = o; o += g_counts[e];
        }
        g_offsets[E_NUM] = o;
    }
}

__global__ void scatter_kernel() {
    int t = blockIdx.x * blockDim.x + threadIdx.x;
    if (t >= T_TOK) return;
#pragma unroll
    for (int k = 0; k < TOPK; k++) {
        int e = g_top_e[t * 2 + k];
        int sidx = atomicAdd(&g_cursor[e], 1);
        g_slot_tok[sidx]  = t;
        g_slot_prob[sidx] = g_top_p[t * 2 + k];
        g_tok_slot[t * 2 + k] = sidx;
    }
}

__global__ void aux_kernel(float* __restrict__ out, int out_size) {
    __shared__ float red[E_NUM][256];
    float ls[E_NUM];
#pragma unroll
    for (int e = 0; e < E_NUM; e++) ls[e] = 0.f;
    for (int t = threadIdx.x; t < T_TOK; t += 256)
#pragma unroll
        for (int e = 0; e < E_NUM; e++) ls[e] += g_probs8[t * E_NUM + e];
#pragma unroll
    for (int e = 0; e < E_NUM; e++) red[e][threadIdx.x] = ls[e];
    __syncthreads();
    for (int st = 128; st > 0; st >>= 1) {
        if (threadIdx.x < st)
#pragma unroll
            for (int e = 0; e < E_NUM; e++)
                red[e][threadIdx.x] += red[e][threadIdx.x + st];
        __syncthreads();
    }
    if (threadIdx.x == 0 && out_size > OUT_ELEMS) {
        float aux = 0.f;
        for (int e = 0; e < E_NUM; e++)
            aux += (red[e][0] / (float)T_TOK) * ((float)g_counts[e] / (float)T_TOK);
        out[OUT_ELEMS] = (float)E_NUM * aux;
    }
}

// ---------------- fp32 -> fp16 round ----------------
__global__ void round_kernel(const float4* __restrict__ src,
                             uint2* __restrict__ hi, int n4) {
    int i = blockIdx.x * blockDim.x + threadIdx.x;
    int stride = gridDim.x * blockDim.x;
    for (; i < n4; i += stride) {
        float4 v = src[i];
        __half h0 = __float2half_rn(v.x), h1 = __float2half_rn(v.y);
        __half h2 = __float2half_rn(v.z), h3 = __float2half_rn(v.w);
        uint2 hv;
        hv.x = (uint32_t)__half_as_ushort(h0) | ((uint32_t)__half_as_ushort(h1) << 16);
        hv.y = (uint32_t)__half_as_ushort(h2) | ((uint32_t)__half_as_ushort(h3) << 16);
        hi[i] = hv;
    }
}

// ---------------- mma.sync grouped expert GEMM (512 threads, fp16 single-pass) ----
// Block tile BM x BN, 16 warps, warp tile 64x32 (warp_m = wid/WN, warp_n = wid%WN).
// K=32 per stage, 4 smem stages, prefetch depth 3, one sync/chunk.
// acc += A*B  (both operands fp16-rounded; fp32 accum).
// smem rows padded to 40 halves (80B) -> conflict-free ldmatrix.

#define KCHUNK 32
#define ROWPAD 40
#define ROWB   (ROWPAD * 2)            // 80 bytes per smem row
#define NSTAGE 4

template <int BM, int BN, int WN, int N_DIM, int K_DIM, bool FC1>
__global__ void __launch_bounds__(512, 1)
expert_gemm_mma2(const __half* __restrict__ A_g,
                 const __half* __restrict__ B_g,
                 const float* __restrict__ bias,
                 __half* __restrict__ H_out,
                 float* __restrict__ Y_out) {
    constexpr int NC = K_DIM / KCHUNK;
    constexpr int OFF_A = 0;
    constexpr int OFF_B = BM * ROWB;
    constexpr int ROWS_TOT = BM + BN;                 // 384
    constexpr int STAGE_B = ROWS_TOT * ROWB;          // 30720
    constexpr int NJ = ROWS_TOT / 128;                // 3 rows per thread

    const int e = blockIdx.z;
    const int row_beg = g_offsets[e];
    const int row_end = g_offsets[e + 1];
    const int m0 = row_beg + blockIdx.y * BM;
    if (m0 >= row_end) return;
    const int n0 = blockIdx.x * BN;

    const __half* B_e = B_g + (size_t)e * N_DIM * K_DIM;
    const float* biasE = bias + e * N_DIM;

    extern __shared__ char smem[];
    const uint32_t smb = smem_u32(smem);
    const int tid = threadIdx.x;
    const int wid = tid >> 5;
    const int lane = tid & 31;
    const int warp_m = wid / WN;
    const int warp_n = wid % WN;

    // ---- per-thread cp.async sources: NJ rows, one 16B chunk each ----
    const int r0 = tid >> 2;          // 0..127
    const int c16 = tid & 3;          // 16B chunk in row
    const int kc8 = c16 * 8;          // element offset (8 halves per 16B)
    const __half* gsrc[NJ];
    uint32_t sOff[NJ];
#pragma unroll
    for (int j = 0; j < NJ; j++) {
        const int r = r0 + 128 * j;
        if (r < BM) {
            int rowg = m0 + r;
            int clr = rowg < row_end ? rowg : (row_end - 1);
            int atok = FC1 ? g_slot_tok[clr] : clr;
            gsrc[j] = A_g + (size_t)atok * K_DIM + kc8;
            sOff[j] = (uint32_t)(OFF_A + r * ROWB + c16 * 16);
        } else {
            int rb = r - BM;
            gsrc[j] = B_e + (size_t)(n0 + rb) * K_DIM + kc8;
            sOff[j] = (uint32_t)(OFF_B + rb * ROWB + c16 * 16);
        }
    }

    // ---- ldmatrix per-thread base byte offsets ----
    const int l15 = lane & 15;
    const uint32_t aFrag = (uint32_t)(OFF_A + (warp_m * 64 + l15) * ROWB + (lane >> 4) * 16);
    const uint32_t bFrag = (uint32_t)(OFF_B + (warp_n * 32 + (l15 & 7)) * ROWB + ((l15 >> 3) & 1) * 16);

    float d[4][4][4];
#pragma unroll
    for (int mi = 0; mi < 4; mi++)
#pragma unroll
        for (int ni = 0; ni < 4; ni++)
#pragma unroll
            for (int q = 0; q < 4; q++) d[mi][ni][q] = 0.f;

#define ISSUE_STAGE(cidx)                                                          \
    do {                                                                           \
        const uint32_t sb = smb + ((cidx) % NSTAGE) * STAGE_B;                     \
        const int kk = (cidx) * KCHUNK;                                            \
        _Pragma("unroll")                                                          \
        for (int j = 0; j < NJ; j++)                                               \
            cp16(sb + sOff[j], gsrc[j] + kk);                                      \
    } while (0)

    // prologue: 3 stages in flight
    ISSUE_STAGE(0); CP_COMMIT();
    ISSUE_STAGE(1); CP_COMMIT();
    ISSUE_STAGE(2); CP_COMMIT();

    for (int c = 0; c < NC; ++c) {
        CP_WAIT_2();       // stage c resident (uniform: one commit per iteration)
        __syncthreads();   // also guards reuse of buffer (c+3)%4 (read last iter)

        if (c + 3 < NC) ISSUE_STAGE(c + 3);
        CP_COMMIT();

        const uint32_t sb = smb + (c % NSTAGE) * STAGE_B;
        const uint32_t aB = sb + aFrag;
        const uint32_t bB = sb + bFrag;

#pragma unroll
        for (int ks = 0; ks < 2; ks++) {
            uint32_t Af[4][4], Bf[4][2];
#pragma unroll
            for (int mi = 0; mi < 4; mi++)
                ldsm_x4(Af[mi], aB + mi * (16 * ROWB) + ks * 32);
#pragma unroll
            for (int ni = 0; ni < 4; ni++)
                ldsm_x2(Bf[ni], bB + ni * (8 * ROWB) + ks * 32);
#pragma unroll
            for (int mi = 0; mi < 4; mi++)
#pragma unroll
                for (int ni = 0; ni < 4; ni++)
                    mma16816(d[mi][ni], Af[mi], Bf[ni]);
        }
    }

    // ---- epilogue ----
    const int rl = lane >> 2;          // 0..7
    const int cl = (lane & 3) * 2;     // 0,2,4,6
#pragma unroll
    for (int mi = 0; mi < 4; mi++) {
#pragma unroll
        for (int half = 0; half < 2; half++) {
            const int row = m0 + warp_m * 64 + mi * 16 + rl + half * 8;
            if (row >= row_end) continue;
            if (FC1) {
#pragma unroll
                for (int ni = 0; ni < 4; ni++) {
                    const int col = n0 + warp_n * 32 + ni * 8 + cl;
                    float v0 = fmaxf(d[mi][ni][half * 2 + 0] + biasE[col], 0.f);
                    float v1 = fmaxf(d[mi][ni][half * 2 + 1] + biasE[col + 1], 0.f);
                    __half h0 = __float2half_rn(v0), h1 = __float2half_rn(v1);
                    uint32_t hp = (uint32_t)__half_as_ushort(h0) |
                                  ((uint32_t)__half_as_ushort(h1) << 16);
                    *(uint32_t*)(H_out + (size_t)row * N_DIM + col) = hp;
                }
            } else {
                const float p = g_slot_prob[row];
#pragma unroll
                for (int ni = 0; ni < 4; ni++) {
                    const int col = n0 + warp_n * 32 + ni * 8 + cl;
                    float2 ov;
                    ov.x = (d[mi][ni][half * 2 + 0] + biasE[col])     * p;
                    ov.y = (d[mi][ni][half * 2 + 1] + biasE[col + 1]) * p;
                    *(float2*)(Y_out + (size_t)row * N_DIM + col) = ov;
                }
            }
        }
    }
#undef ISSUE_STAGE
}

#define SMEM_TOTAL2 (NSTAGE * (128 + 256) * ROWB)   // 122880 (both shapes)

// ---------------- combine ----------------
__global__ void combine_kernel(float* __restrict__ out) {
    const int t = blockIdx.x;
    const int s0 = g_tok_slot[t * 2 + 0];
    const int s1 = g_tok_slot[t * 2 + 1];
    const float4* y0 = (const float4*)(g_Y + (size_t)s0 * D_DIM);
    const float4* y1 = (const float4*)(g_Y + (size_t)s1 * D_DIM);
    float4* o = (float4*)(out + (size_t)t * D_DIM);
    int i = threadIdx.x;
    float4 a = y0[i], b = y1[i];
    o[i] = make_float4(a.x + b.x, a.y + b.y, a.z + b.z, a.w + b.w);
}

// ---------------- launch ----------------
extern "C" void kernel_launch(void* const* d_in, const int* in_sizes, int n_in,
                              void* d_out, int out_size) {
    const float* x  = (const float*)d_in[0];   // [2,1024,1024]
    const float* Wg = (const float*)d_in[1];   // [8,1024]
    const float* W1 = (const float*)d_in[2];   // [8,4096,1024]
    const float* b1 = (const float*)d_in[3];   // [8,4096]
    const float* W2 = (const float*)d_in[4];   // [8,1024,4096]
    const float* b2 = (const float*)d_in[5];   // [8,1024]
    float* out = (float*)d_out;

    void *p_xh, *p_w1h, *p_w2h, *p_hh, *p_y;
    cudaGetSymbolAddress(&p_xh, g_xh);
    cudaGetSymbolAddress(&p_w1h, g_W1h);
    cudaGetSymbolAddress(&p_w2h, g_W2h);
    cudaGetSymbolAddress(&p_hh, g_Hh);
    cudaGetSymbolAddress(&p_y, g_Y);

    cudaFuncSetAttribute(expert_gemm_mma2<128, 256, 8, H_DIM, D_DIM, true>,
                         cudaFuncAttributeMaxDynamicSharedMemorySize, SMEM_TOTAL2);
    cudaFuncSetAttribute(expert_gemm_mma2<256, 128, 4, D_DIM, H_DIM, false>,
                         cudaFuncAttributeMaxDynamicSharedMemorySize, SMEM_TOTAL2);

    init_kernel<<<1, 32>>>();
    router_kernel<<<T_TOK, 128>>>(x, Wg);
    offsets_kernel<<<1, 32>>>();
    scatter_kernel<<<(T_TOK + 255) / 256, 256>>>();
    aux_kernel<<<1, 256>>>(out, out_size);

    round_kernel<<<512, 256>>>((const float4*)x, (uint2*)p_xh,
                               (int)((size_t)T_TOK * D_DIM / 4));
    round_kernel<<<2048, 256>>>((const float4*)W1, (uint2*)p_w1h,
                                (int)((size_t)E_NUM * H_DIM * D_DIM / 4));
    round_kernel<<<2048, 256>>>((const float4*)W2, (uint2*)p_w2h,
                                (int)((size_t)E_NUM * D_DIM * H_DIM / 4));

    // fc1: x[gathered] @ W1^T -> relu -> Hh   (tile 128x256)
    {
        dim3 grid(H_DIM / 256, T_TOK / 128, E_NUM);
        expert_gemm_mma2<128, 256, 8, H_DIM, D_DIM, true><<<grid, 512, SMEM_TOTAL2>>>(
            (const __half*)p_xh, (const __half*)p_w1h, b1, (__half*)p_hh, nullptr);
    }
    // fc2: H @ W2^T -> *prob -> Y   (tile 256x128)
    {
        dim3 grid(D_DIM / 128, T_TOK / 256, E_NUM);
        expert_gemm_mma2<256, 128, 4, D_DIM, H_DIM, false><<<grid, 512, SMEM_TOTAL2>>>(
            (const __half*)p_hh, (const __half*)p_w2h, b2, nullptr, (float*)p_y);
    }
    combine_kernel<<<T_TOK, 256>>>(out);
}